// round 3
// baseline (speedup 1.0000x reference)
#include <cuda_runtime.h>
#include <math.h>

#define Tt  4096
#define Bb  8
#define Dd  512
#define Hh  8
#define NBn 64
#define BSs 64
#define DHh 64
#define TBr (Tt*Bb)          // 32768 rows
#define LNEPS 1e-5f

// ---------------- scratch: single static arena, manually carved -------------
// layout (floats):
//   [0      , 16M)  xc   conv+bn output (residual for LN1)
//   [16M    , 32M)  q    | later reused as t1 (gemm temp after attention)
//   [32M    , 48M)  k    | later reused as h (MLP hidden, spans k+v = 32M)
//   [48M    , 64M)  v    |
//   [64M    , 80M)  o    attention output
//   [80M    , 96M)  x1   after LN1
#define SEG ((size_t)TBr * Dd)          // 16,777,216 floats
__device__ float g_scratch[SEG * 6];

// ---------------- conv (depthwise, k=3, pad 1, cross-correlation) + residual + BN
__global__ void conv_bn_kernel(const float* __restrict__ x,
                               const float* __restrict__ w,   // [D,1,3]
                               const float* __restrict__ gg,
                               const float* __restrict__ bb,
                               const float* __restrict__ mm,
                               const float* __restrict__ vv,
                               float* __restrict__ out) {
    int idx = blockIdx.x * blockDim.x + threadIdx.x;
    if (idx >= TBr * Dd) return;
    int d = idx % Dd;
    int t = idx / (Bb * Dd);
    float xm = (t > 0)      ? x[idx - Bb * Dd] : 0.f;
    float xc = x[idx];
    float xp = (t < Tt - 1) ? x[idx + Bb * Dd] : 0.f;
    float y = fmaf(w[d*3+0], xm, fmaf(w[d*3+1], xc, w[d*3+2] * xp)) + xc;
    y = (y - mm[d]) * rsqrtf(vv[d] + LNEPS) * gg[d] + bb[d];
    out[idx] = y;
}

// ---------------- classic fp32 SGEMM: C[M,N] = A[M,K] @ W[K,N] + bias, opt GeLU
#define GBM 128
#define GBN 128
#define GBK 8
#define GTM 8
#define GTN 8

template<int GELU>
__global__ void __launch_bounds__(256)
sgemm_kernel(int M, int N, int K,
             const float* __restrict__ A, const float* __restrict__ W,
             const float* __restrict__ bias, float* __restrict__ C) {
    __shared__ float As[GBK][GBM];
    __shared__ float Bs[GBK][GBN];
    const int bx = blockIdx.x;   // N tile
    const int by = blockIdx.y;   // M tile
    const int tid = threadIdx.x;
    const int tcol = tid & 15;
    const int trow = tid >> 4;

    const int aRow = tid >> 1;
    const int aCol = (tid & 1) * 4;
    const int bRow = tid >> 5;
    const int bCol = (tid & 31) * 4;

    const float* Aptr = A + (size_t)(by * GBM) * K;
    const float* Bptr = W + bx * GBN;

    float acc[GTM][GTN];
    #pragma unroll
    for (int i = 0; i < GTM; i++)
        #pragma unroll
        for (int j = 0; j < GTN; j++) acc[i][j] = 0.f;

    for (int k0 = 0; k0 < K; k0 += GBK) {
        float4 a4 = *(const float4*)(Aptr + (size_t)aRow * K + k0 + aCol);
        As[aCol + 0][aRow] = a4.x;
        As[aCol + 1][aRow] = a4.y;
        As[aCol + 2][aRow] = a4.z;
        As[aCol + 3][aRow] = a4.w;
        float4 b4 = *(const float4*)(Bptr + (size_t)(k0 + bRow) * N + bCol);
        *(float4*)&Bs[bRow][bCol] = b4;
        __syncthreads();

        #pragma unroll
        for (int k = 0; k < GBK; k++) {
            float regM[GTM], regN[GTN];
            #pragma unroll
            for (int i = 0; i < GTM; i++) regM[i] = As[k][trow * GTM + i];
            #pragma unroll
            for (int j = 0; j < GTN; j++) regN[j] = Bs[k][tcol * GTN + j];
            #pragma unroll
            for (int i = 0; i < GTM; i++)
                #pragma unroll
                for (int j = 0; j < GTN; j++)
                    acc[i][j] = fmaf(regM[i], regN[j], acc[i][j]);
        }
        __syncthreads();
    }

    #pragma unroll
    for (int i = 0; i < GTM; i++) {
        int row = by * GBM + trow * GTM + i;
        #pragma unroll
        for (int j = 0; j < GTN; j += 4) {
            int col = bx * GBN + tcol * GTN + j;
            float4 r;
            r.x = acc[i][j + 0] + bias[col + 0];
            r.y = acc[i][j + 1] + bias[col + 1];
            r.z = acc[i][j + 2] + bias[col + 2];
            r.w = acc[i][j + 3] + bias[col + 3];
            if (GELU) {
                r.x = r.x * 0.5f * (1.f + erff(r.x * 0.70710678118654752f));
                r.y = r.y * 0.5f * (1.f + erff(r.y * 0.70710678118654752f));
                r.z = r.z * 0.5f * (1.f + erff(r.z * 0.70710678118654752f));
                r.w = r.w * 0.5f * (1.f + erff(r.w * 0.70710678118654752f));
            }
            *(float4*)(C + (size_t)row * N + col) = r;
        }
    }
}

// ---------------- bucketed attention: one CTA per (n, h, b)
#define ATTN_SMEM ((64*65 + 128*65 + 64*128) * 4)

__global__ void __launch_bounds__(256)
attn_kernel(const float* __restrict__ q, const float* __restrict__ k,
            const float* __restrict__ v, const int* __restrict__ t_len,
            const int* __restrict__ ridx, float* __restrict__ o) {
    const int n = blockIdx.x, h = blockIdx.y, b = blockIdx.z;
    extern __shared__ float sm[];
    float (*Qs)[65]  = (float(*)[65])sm;
    float (*KVs)[65] = (float(*)[65])(sm + 64 * 65);
    float (*Ps)[128] = (float(*)[128])(sm + 64 * 65 + 128 * 65);

    const int tid = threadIdx.x;
    const int tlen = t_len[b];
    const int rn = ridx[n];
    const int chan = h * DHh;

    for (int it = tid; it < 64 * 16; it += 256) {
        int r = it >> 4, c4 = (it & 15) * 4;
        int t = n * BSs + r;
        float4 val = *(const float4*)(q + ((size_t)t * Bb + b) * Dd + chan + c4);
        Qs[r][c4] = val.x; Qs[r][c4+1] = val.y; Qs[r][c4+2] = val.z; Qs[r][c4+3] = val.w;
    }
    for (int it = tid; it < 128 * 16; it += 256) {
        int r = it >> 4, c4 = (it & 15) * 4;
        int t = (r < 64) ? n * BSs + r : rn * BSs + (r - 64);
        float4 val = *(const float4*)(k + ((size_t)t * Bb + b) * Dd + chan + c4);
        KVs[r][c4] = val.x; KVs[r][c4+1] = val.y; KVs[r][c4+2] = val.z; KVs[r][c4+3] = val.w;
    }
    __syncthreads();

    {
        const int i0 = (tid >> 4) * 4;
        const int jl = tid & 15;
        float acc[4][8];
        #pragma unroll
        for (int ii = 0; ii < 4; ii++)
            #pragma unroll
            for (int jj = 0; jj < 8; jj++) acc[ii][jj] = 0.f;

        #pragma unroll 16
        for (int dh = 0; dh < 64; dh++) {
            float qr[4], kr[8];
            #pragma unroll
            for (int ii = 0; ii < 4; ii++) qr[ii] = Qs[i0 + ii][dh];
            #pragma unroll
            for (int jj = 0; jj < 8; jj++) kr[jj] = KVs[jl + jj * 16][dh];
            #pragma unroll
            for (int ii = 0; ii < 4; ii++)
                #pragma unroll
                for (int jj = 0; jj < 8; jj++)
                    acc[ii][jj] = fmaf(qr[ii], kr[jj], acc[ii][jj]);
        }
        #pragma unroll
        for (int jj = 0; jj < 8; jj++) {
            int j = jl + jj * 16;
            int kp = (j < 64) ? n * BSs + j : rn * BSs + (j - 64);
            bool valid = kp < tlen;
            #pragma unroll
            for (int ii = 0; ii < 4; ii++)
                Ps[i0 + ii][j] = valid ? acc[ii][jj] * 0.125f : -1e9f;
        }
    }
    __syncthreads();

    {
        const int warp = tid >> 5, lane = tid & 31;
        for (int r = warp * 8; r < warp * 8 + 8; r++) {
            float v0 = Ps[r][lane], v1 = Ps[r][lane + 32];
            float v2 = Ps[r][lane + 64], v3 = Ps[r][lane + 96];
            float mx = fmaxf(fmaxf(v0, v1), fmaxf(v2, v3));
            #pragma unroll
            for (int off = 16; off; off >>= 1) mx = fmaxf(mx, __shfl_xor_sync(~0u, mx, off));
            v0 = expf(v0 - mx); v1 = expf(v1 - mx);
            v2 = expf(v2 - mx); v3 = expf(v3 - mx);
            float s = v0 + v1 + v2 + v3;
            #pragma unroll
            for (int off = 16; off; off >>= 1) s += __shfl_xor_sync(~0u, s, off);
            float inv = 1.f / s;
            Ps[r][lane]      = v0 * inv;
            Ps[r][lane + 32] = v1 * inv;
            Ps[r][lane + 64] = v2 * inv;
            Ps[r][lane + 96] = v3 * inv;
        }
    }
    __syncthreads();

    for (int it = tid; it < 128 * 16; it += 256) {
        int r = it >> 4, c4 = (it & 15) * 4;
        int t = (r < 64) ? n * BSs + r : rn * BSs + (r - 64);
        float4 val = *(const float4*)(v + ((size_t)t * Bb + b) * Dd + chan + c4);
        KVs[r][c4] = val.x; KVs[r][c4+1] = val.y; KVs[r][c4+2] = val.z; KVs[r][c4+3] = val.w;
    }
    __syncthreads();

    {
        const int i0 = (tid >> 4) * 4;
        const int dh0 = (tid & 15) * 4;
        float acc[4][4];
        #pragma unroll
        for (int ii = 0; ii < 4; ii++)
            #pragma unroll
            for (int c = 0; c < 4; c++) acc[ii][c] = 0.f;

        #pragma unroll 8
        for (int j = 0; j < 128; j++) {
            float pr[4], vr[4];
            #pragma unroll
            for (int ii = 0; ii < 4; ii++) pr[ii] = Ps[i0 + ii][j];
            #pragma unroll
            for (int c = 0; c < 4; c++) vr[c] = KVs[j][dh0 + c];
            #pragma unroll
            for (int ii = 0; ii < 4; ii++)
                #pragma unroll
                for (int c = 0; c < 4; c++)
                    acc[ii][c] = fmaf(pr[ii], vr[c], acc[ii][c]);
        }
        #pragma unroll
        for (int ii = 0; ii < 4; ii++) {
            int t = n * BSs + i0 + ii;
            float4 r;
            r.x = acc[ii][0]; r.y = acc[ii][1]; r.z = acc[ii][2]; r.w = acc[ii][3];
            *(float4*)(o + ((size_t)t * Bb + b) * Dd + chan + dh0) = r;
        }
    }
}

// ---------------- residual + LayerNorm --------------------------------------
__global__ void __launch_bounds__(128)
res_ln_kernel(const float* __restrict__ a, const float* __restrict__ res,
              const float* __restrict__ g, const float* __restrict__ bt,
              float* __restrict__ out) {
    const int row = blockIdx.x;
    const int tid = threadIdx.x;
    const size_t base = (size_t)row * Dd;

    float4 va = *(const float4*)(a   + base + tid * 4);
    float4 vr = *(const float4*)(res + base + tid * 4);
    float x0 = va.x + vr.x, x1 = va.y + vr.y, x2 = va.z + vr.z, x3 = va.w + vr.w;

    float s  = x0 + x1 + x2 + x3;
    float sq = x0*x0 + x1*x1 + x2*x2 + x3*x3;

    const int lane = tid & 31, warp = tid >> 5;
    #pragma unroll
    for (int off = 16; off; off >>= 1) {
        s  += __shfl_xor_sync(~0u, s, off);
        sq += __shfl_xor_sync(~0u, sq, off);
    }
    __shared__ float ss[4], sqs[4];
    if (lane == 0) { ss[warp] = s; sqs[warp] = sq; }
    __syncthreads();
    s  = ss[0] + ss[1] + ss[2] + ss[3];
    sq = sqs[0] + sqs[1] + sqs[2] + sqs[3];

    float mean = s * (1.f / Dd);
    float var  = sq * (1.f / Dd) - mean * mean;
    float rs   = rsqrtf(var + LNEPS);

    float4 gg = *(const float4*)(g  + tid * 4);
    float4 bb = *(const float4*)(bt + tid * 4);
    float4 r;
    r.x = (x0 - mean) * rs * gg.x + bb.x;
    r.y = (x1 - mean) * rs * gg.y + bb.y;
    r.z = (x2 - mean) * rs * gg.z + bb.z;
    r.w = (x3 - mean) * rs * gg.w + bb.w;
    *(float4*)(out + base + tid * 4) = r;
}

// ---------------- launch ----------------------------------------------------
extern "C" void kernel_launch(void* const* d_in, const int* in_sizes, int n_in,
                              void* d_out, int out_size) {
    const float* x        = (const float*)d_in[0];
    const int*   t_length = (const int*)  d_in[1];
    const int*   rand_idx = (const int*)  d_in[2];
    const float* conv_w   = (const float*)d_in[3];
    const float* bn_g     = (const float*)d_in[4];
    const float* bn_b     = (const float*)d_in[5];
    const float* bn_m     = (const float*)d_in[6];
    const float* bn_v     = (const float*)d_in[7];
    const float* wq = (const float*)d_in[8];  const float* bq = (const float*)d_in[9];
    const float* wk = (const float*)d_in[10]; const float* bk = (const float*)d_in[11];
    const float* wv = (const float*)d_in[12]; const float* bv = (const float*)d_in[13];
    const float* wo = (const float*)d_in[14]; const float* bo = (const float*)d_in[15];
    const float* ln1_g = (const float*)d_in[16]; const float* ln1_b = (const float*)d_in[17];
    const float* w1 = (const float*)d_in[18]; const float* b1 = (const float*)d_in[19];
    const float* w2 = (const float*)d_in[20]; const float* b2 = (const float*)d_in[21];
    const float* ln2_g = (const float*)d_in[22]; const float* ln2_b = (const float*)d_in[23];
    float* out = (float*)d_out;

    // one-time host-side setup (not stream work; keeps the capture call
    // launches-only). Deterministic: same pointers every call.
    static float* p_base = nullptr;
    if (p_base == nullptr) {
        cudaGetSymbolAddress((void**)&p_base, g_scratch);
        cudaFuncSetAttribute((const void*)attn_kernel,
                             cudaFuncAttributeMaxDynamicSharedMemorySize, ATTN_SMEM);
    }
    float* p_xc = p_base;
    float* p_q  = p_base + SEG;       // reused as t1 after attention
    float* p_k  = p_base + SEG * 2;   // reused as h (spans k+v) after attention
    float* p_v  = p_base + SEG * 3;
    float* p_o  = p_base + SEG * 4;
    float* p_x1 = p_base + SEG * 5;
    float* p_t1 = p_q;
    float* p_h  = p_k;

    // 1) conv + residual + BN
    conv_bn_kernel<<<(TBr * Dd) / 256, 256>>>(x, conv_w, bn_g, bn_b, bn_m, bn_v, p_xc);

    // 2) QKV projections
    {
        dim3 grid(Dd / GBN, TBr / GBM);
        sgemm_kernel<0><<<grid, 256>>>(TBr, Dd, Dd, p_xc, wq, bq, p_q);
        sgemm_kernel<0><<<grid, 256>>>(TBr, Dd, Dd, p_xc, wk, bk, p_k);
        sgemm_kernel<0><<<grid, 256>>>(TBr, Dd, Dd, p_xc, wv, bv, p_v);
    }

    // 3) bucketed attention
    {
        dim3 grid(NBn, Hh, Bb);
        attn_kernel<<<grid, 256, ATTN_SMEM>>>(p_q, p_k, p_v, t_length, rand_idx, p_o);
    }

    // 4) O projection (t1 aliases q — q is dead now)
    {
        dim3 grid(Dd / GBN, TBr / GBM);
        sgemm_kernel<0><<<grid, 256>>>(TBr, Dd, Dd, p_o, wo, bo, p_t1);
    }

    // 5) residual + LN1
    res_ln_kernel<<<TBr, 128>>>(p_t1, p_xc, ln1_g, ln1_b, p_x1);

    // 6) MLP up (GeLU fused; h aliases k|v — both dead now)
    {
        dim3 grid((2 * Dd) / GBN, TBr / GBM);
        sgemm_kernel<1><<<grid, 256>>>(TBr, 2 * Dd, Dd, p_x1, w1, b1, p_h);
    }

    // 7) MLP down
    {
        dim3 grid(Dd / GBN, TBr / GBM);
        sgemm_kernel<0><<<grid, 256>>>(TBr, Dd, 2 * Dd, p_h, w2, b2, p_t1);
    }

    // 8) residual + LN2 -> output
    res_ln_kernel<<<TBr, 128>>>(p_t1, p_x1, ln2_g, ln2_b, out);
}

// round 6
// speedup vs baseline: 2.3629x; 2.3629x over previous
#include <cuda_runtime.h>
#include <math.h>
#include <stdint.h>

#define Tt  4096
#define Bb  8
#define Dd  512
#define Hh  8
#define NBn 64
#define BSs 64
#define DHh 64
#define TBr (Tt*Bb)          // 32768 rows
#define LNEPS 1e-5f

// ---------------- scratch: single static arena, manually carved -------------
#define SEG ((size_t)TBr * Dd)          // 16,777,216 floats
__device__ float g_scratch[SEG * 6];

// ---------------- conv (depthwise, k=3, pad 1) + residual + BN ---------------
__global__ void conv_bn_kernel(const float* __restrict__ x,
                               const float* __restrict__ w,   // [D,1,3]
                               const float* __restrict__ gg,
                               const float* __restrict__ bb,
                               const float* __restrict__ mm,
                               const float* __restrict__ vv,
                               float* __restrict__ out) {
    int idx = blockIdx.x * blockDim.x + threadIdx.x;
    if (idx >= TBr * Dd) return;
    int d = idx % Dd;
    int t = idx / (Bb * Dd);
    float xm = (t > 0)      ? x[idx - Bb * Dd] : 0.f;
    float xc = x[idx];
    float xp = (t < Tt - 1) ? x[idx + Bb * Dd] : 0.f;
    float y = fmaf(w[d*3+0], xm, fmaf(w[d*3+1], xc, w[d*3+2] * xp)) + xc;
    y = (y - mm[d]) * rsqrtf(vv[d] + LNEPS) * gg[d] + bb[d];
    out[idx] = y;
}

// ---------------- TF32 tensor-core GEMM: C[M,N] = A[M,K] @ W[K,N] + bias -----
// 128x128x32 CTA tile, 256 threads (8 warps), warp = 32x64, mma.m16n8k8.tf32.
// As padded to 36 floats/row, Bs padded to 136 -> conflict-free fragment LDS.

__device__ __forceinline__ uint32_t f2tf32(float f) {
    uint32_t r;
    asm("cvt.rna.tf32.f32 %0, %1;" : "=r"(r) : "f"(f));
    return r;
}

__device__ __forceinline__ void mma_tf32(float* d, const uint32_t* a, const uint32_t* b) {
    asm volatile(
        "mma.sync.aligned.m16n8k8.row.col.f32.tf32.tf32.f32 "
        "{%0,%1,%2,%3}, {%4,%5,%6,%7}, {%8,%9}, {%0,%1,%2,%3};\n"
        : "+f"(d[0]), "+f"(d[1]), "+f"(d[2]), "+f"(d[3])
        : "r"(a[0]), "r"(a[1]), "r"(a[2]), "r"(a[3]),
          "r"(b[0]), "r"(b[1]));
}

template<int GELU>
__global__ void __launch_bounds__(256)
mma_gemm_kernel(int M, int N, int K,
                const float* __restrict__ A, const float* __restrict__ W,
                const float* __restrict__ bias, float* __restrict__ C) {
    __shared__ float As[128][36];   // [m][k], pad 36 -> bank = (4g+t) distinct
    __shared__ float Bs[32][136];   // [k][n], pad 136 -> bank = (8t+g) distinct

    const int tid = threadIdx.x;
    const int m0 = blockIdx.y * 128;
    const int n0 = blockIdx.x * 128;
    const int wid  = tid >> 5, lane = tid & 31;
    const int g = lane >> 2, t = lane & 3;
    const int rb = (wid >> 1) * 32;      // warp row base within tile (0..96)
    const int cb = (wid & 1) * 64;       // warp col base within tile (0 or 64)

    // global-load mapping
    const int arow = tid >> 3;           // 0..31 (+i*32)
    const int acol = (tid & 7) * 4;      // 0..28
    const int bkr  = tid >> 5;           // 0..7  (+i*8)
    const int bcol = (tid & 31) * 4;     // 0..124

    float acc[2][8][4];
    #pragma unroll
    for (int mt = 0; mt < 2; mt++)
        #pragma unroll
        for (int nt = 0; nt < 8; nt++)
            #pragma unroll
            for (int c = 0; c < 4; c++) acc[mt][nt][c] = 0.f;

    const int NIT = K / 32;
    float4 ar[4], br[4];

    // prologue: load tile 0 and stage to smem
    #pragma unroll
    for (int i = 0; i < 4; i++) {
        ar[i] = *(const float4*)(A + (size_t)(m0 + arow + i * 32) * K + acol);
        br[i] = *(const float4*)(W + (size_t)(bkr + i * 8) * N + n0 + bcol);
    }
    #pragma unroll
    for (int i = 0; i < 4; i++) {
        float* as = &As[arow + i * 32][acol];
        as[0] = __uint_as_float(f2tf32(ar[i].x));
        as[1] = __uint_as_float(f2tf32(ar[i].y));
        as[2] = __uint_as_float(f2tf32(ar[i].z));
        as[3] = __uint_as_float(f2tf32(ar[i].w));
        float* bs = &Bs[bkr + i * 8][bcol];
        bs[0] = __uint_as_float(f2tf32(br[i].x));
        bs[1] = __uint_as_float(f2tf32(br[i].y));
        bs[2] = __uint_as_float(f2tf32(br[i].z));
        bs[3] = __uint_as_float(f2tf32(br[i].w));
    }
    __syncthreads();

    #pragma unroll 1
    for (int it = 0; it < NIT; it++) {
        const bool has_next = (it + 1 < NIT);
        if (has_next) {
            const int k0 = (it + 1) * 32;
            #pragma unroll
            for (int i = 0; i < 4; i++) {
                ar[i] = *(const float4*)(A + (size_t)(m0 + arow + i * 32) * K + k0 + acol);
                br[i] = *(const float4*)(W + (size_t)(k0 + bkr + i * 8) * N + n0 + bcol);
            }
        }

        // compute on current smem tile: 4 k-steps of k8
        #pragma unroll
        for (int ks = 0; ks < 4; ks++) {
            const int k8 = ks * 8;
            uint32_t af[2][4];
            #pragma unroll
            for (int mt = 0; mt < 2; mt++) {
                const int r = rb + mt * 16 + g;
                af[mt][0] = __float_as_uint(As[r    ][k8 + t    ]);
                af[mt][1] = __float_as_uint(As[r + 8][k8 + t    ]);
                af[mt][2] = __float_as_uint(As[r    ][k8 + t + 4]);
                af[mt][3] = __float_as_uint(As[r + 8][k8 + t + 4]);
            }
            uint32_t bf[8][2];
            #pragma unroll
            for (int nt = 0; nt < 8; nt++) {
                const int c = cb + nt * 8 + g;
                bf[nt][0] = __float_as_uint(Bs[k8 + t    ][c]);
                bf[nt][1] = __float_as_uint(Bs[k8 + t + 4][c]);
            }
            #pragma unroll
            for (int mt = 0; mt < 2; mt++)
                #pragma unroll
                for (int nt = 0; nt < 8; nt++)
                    mma_tf32(acc[mt][nt], af[mt], bf[nt]);
        }

        if (has_next) {
            __syncthreads();
            #pragma unroll
            for (int i = 0; i < 4; i++) {
                float* as = &As[arow + i * 32][acol];
                as[0] = __uint_as_float(f2tf32(ar[i].x));
                as[1] = __uint_as_float(f2tf32(ar[i].y));
                as[2] = __uint_as_float(f2tf32(ar[i].z));
                as[3] = __uint_as_float(f2tf32(ar[i].w));
                float* bs = &Bs[bkr + i * 8][bcol];
                bs[0] = __uint_as_float(f2tf32(br[i].x));
                bs[1] = __uint_as_float(f2tf32(br[i].y));
                bs[2] = __uint_as_float(f2tf32(br[i].z));
                bs[3] = __uint_as_float(f2tf32(br[i].w));
            }
            __syncthreads();
        }
    }

    // epilogue: bias (+ optional exact GeLU), write float2 pairs
    #pragma unroll
    for (int mt = 0; mt < 2; mt++) {
        const int r0 = m0 + rb + mt * 16 + g;
        #pragma unroll
        for (int nt = 0; nt < 8; nt++) {
            const int c = n0 + cb + nt * 8 + 2 * t;
            const float b0 = bias[c], b1 = bias[c + 1];
            float v0 = acc[mt][nt][0] + b0;
            float v1 = acc[mt][nt][1] + b1;
            float v2 = acc[mt][nt][2] + b0;
            float v3 = acc[mt][nt][3] + b1;
            if (GELU) {
                v0 = v0 * 0.5f * (1.f + erff(v0 * 0.70710678118654752f));
                v1 = v1 * 0.5f * (1.f + erff(v1 * 0.70710678118654752f));
                v2 = v2 * 0.5f * (1.f + erff(v2 * 0.70710678118654752f));
                v3 = v3 * 0.5f * (1.f + erff(v3 * 0.70710678118654752f));
            }
            float2 p0; p0.x = v0; p0.y = v1;
            float2 p1; p1.x = v2; p1.y = v3;
            *(float2*)(C + (size_t)r0 * N + c)       = p0;
            *(float2*)(C + (size_t)(r0 + 8) * N + c) = p1;
        }
    }
}

// ---------------- bucketed attention: one CTA per (n, h, b) ------------------
#define ATTN_SMEM ((64*65 + 128*65 + 64*128) * 4)

__global__ void __launch_bounds__(256)
attn_kernel(const float* __restrict__ q, const float* __restrict__ k,
            const float* __restrict__ v, const int* __restrict__ t_len,
            const int* __restrict__ ridx, float* __restrict__ o) {
    const int n = blockIdx.x, h = blockIdx.y, b = blockIdx.z;
    extern __shared__ float sm[];
    float (*Qs)[65]  = (float(*)[65])sm;
    float (*KVs)[65] = (float(*)[65])(sm + 64 * 65);
    float (*Ps)[128] = (float(*)[128])(sm + 64 * 65 + 128 * 65);

    const int tid = threadIdx.x;
    const int tlen = t_len[b];
    const int rn = ridx[n];
    const int chan = h * DHh;

    for (int it = tid; it < 64 * 16; it += 256) {
        int r = it >> 4, c4 = (it & 15) * 4;
        int t = n * BSs + r;
        float4 val = *(const float4*)(q + ((size_t)t * Bb + b) * Dd + chan + c4);
        Qs[r][c4] = val.x; Qs[r][c4+1] = val.y; Qs[r][c4+2] = val.z; Qs[r][c4+3] = val.w;
    }
    for (int it = tid; it < 128 * 16; it += 256) {
        int r = it >> 4, c4 = (it & 15) * 4;
        int t = (r < 64) ? n * BSs + r : rn * BSs + (r - 64);
        float4 val = *(const float4*)(k + ((size_t)t * Bb + b) * Dd + chan + c4);
        KVs[r][c4] = val.x; KVs[r][c4+1] = val.y; KVs[r][c4+2] = val.z; KVs[r][c4+3] = val.w;
    }
    __syncthreads();

    {
        const int i0 = (tid >> 4) * 4;
        const int jl = tid & 15;
        float acc[4][8];
        #pragma unroll
        for (int ii = 0; ii < 4; ii++)
            #pragma unroll
            for (int jj = 0; jj < 8; jj++) acc[ii][jj] = 0.f;

        #pragma unroll 16
        for (int dh = 0; dh < 64; dh++) {
            float qr[4], kr[8];
            #pragma unroll
            for (int ii = 0; ii < 4; ii++) qr[ii] = Qs[i0 + ii][dh];
            #pragma unroll
            for (int jj = 0; jj < 8; jj++) kr[jj] = KVs[jl + jj * 16][dh];
            #pragma unroll
            for (int ii = 0; ii < 4; ii++)
                #pragma unroll
                for (int jj = 0; jj < 8; jj++)
                    acc[ii][jj] = fmaf(qr[ii], kr[jj], acc[ii][jj]);
        }
        #pragma unroll
        for (int jj = 0; jj < 8; jj++) {
            int j = jl + jj * 16;
            int kp = (j < 64) ? n * BSs + j : rn * BSs + (j - 64);
            bool valid = kp < tlen;
            #pragma unroll
            for (int ii = 0; ii < 4; ii++)
                Ps[i0 + ii][j] = valid ? acc[ii][jj] * 0.125f : -1e9f;
        }
    }
    __syncthreads();

    {
        const int warp = tid >> 5, lane = tid & 31;
        for (int r = warp * 8; r < warp * 8 + 8; r++) {
            float v0 = Ps[r][lane], v1 = Ps[r][lane + 32];
            float v2 = Ps[r][lane + 64], v3 = Ps[r][lane + 96];
            float mx = fmaxf(fmaxf(v0, v1), fmaxf(v2, v3));
            #pragma unroll
            for (int off = 16; off; off >>= 1) mx = fmaxf(mx, __shfl_xor_sync(~0u, mx, off));
            v0 = expf(v0 - mx); v1 = expf(v1 - mx);
            v2 = expf(v2 - mx); v3 = expf(v3 - mx);
            float s = v0 + v1 + v2 + v3;
            #pragma unroll
            for (int off = 16; off; off >>= 1) s += __shfl_xor_sync(~0u, s, off);
            float inv = 1.f / s;
            Ps[r][lane]      = v0 * inv;
            Ps[r][lane + 32] = v1 * inv;
            Ps[r][lane + 64] = v2 * inv;
            Ps[r][lane + 96] = v3 * inv;
        }
    }
    __syncthreads();

    for (int it = tid; it < 128 * 16; it += 256) {
        int r = it >> 4, c4 = (it & 15) * 4;
        int t = (r < 64) ? n * BSs + r : rn * BSs + (r - 64);
        float4 val = *(const float4*)(v + ((size_t)t * Bb + b) * Dd + chan + c4);
        KVs[r][c4] = val.x; KVs[r][c4+1] = val.y; KVs[r][c4+2] = val.z; KVs[r][c4+3] = val.w;
    }
    __syncthreads();

    {
        const int i0 = (tid >> 4) * 4;
        const int dh0 = (tid & 15) * 4;
        float acc[4][4];
        #pragma unroll
        for (int ii = 0; ii < 4; ii++)
            #pragma unroll
            for (int c = 0; c < 4; c++) acc[ii][c] = 0.f;

        #pragma unroll 8
        for (int j = 0; j < 128; j++) {
            float pr[4], vr[4];
            #pragma unroll
            for (int ii = 0; ii < 4; ii++) pr[ii] = Ps[i0 + ii][j];
            #pragma unroll
            for (int c = 0; c < 4; c++) vr[c] = KVs[j][dh0 + c];
            #pragma unroll
            for (int ii = 0; ii < 4; ii++)
                #pragma unroll
                for (int c = 0; c < 4; c++)
                    acc[ii][c] = fmaf(pr[ii], vr[c], acc[ii][c]);
        }
        #pragma unroll
        for (int ii = 0; ii < 4; ii++) {
            int t = n * BSs + i0 + ii;
            float4 r;
            r.x = acc[ii][0]; r.y = acc[ii][1]; r.z = acc[ii][2]; r.w = acc[ii][3];
            *(float4*)(o + ((size_t)t * Bb + b) * Dd + chan + dh0) = r;
        }
    }
}

// ---------------- residual + LayerNorm --------------------------------------
__global__ void __launch_bounds__(128)
res_ln_kernel(const float* __restrict__ a, const float* __restrict__ res,
              const float* __restrict__ g, const float* __restrict__ bt,
              float* __restrict__ out) {
    const int row = blockIdx.x;
    const int tid = threadIdx.x;
    const size_t base = (size_t)row * Dd;

    float4 va = *(const float4*)(a   + base + tid * 4);
    float4 vr = *(const float4*)(res + base + tid * 4);
    float x0 = va.x + vr.x, x1 = va.y + vr.y, x2 = va.z + vr.z, x3 = va.w + vr.w;

    float s  = x0 + x1 + x2 + x3;
    float sq = x0*x0 + x1*x1 + x2*x2 + x3*x3;

    const int lane = tid & 31, warp = tid >> 5;
    #pragma unroll
    for (int off = 16; off; off >>= 1) {
        s  += __shfl_xor_sync(~0u, s, off);
        sq += __shfl_xor_sync(~0u, sq, off);
    }
    __shared__ float ss[4], sqs[4];
    if (lane == 0) { ss[warp] = s; sqs[warp] = sq; }
    __syncthreads();
    s  = ss[0] + ss[1] + ss[2] + ss[3];
    sq = sqs[0] + sqs[1] + sqs[2] + sqs[3];

    float mean = s * (1.f / Dd);
    float var  = sq * (1.f / Dd) - mean * mean;
    float rs   = rsqrtf(var + LNEPS);

    float4 gg = *(const float4*)(g  + tid * 4);
    float4 bb = *(const float4*)(bt + tid * 4);
    float4 r;
    r.x = (x0 - mean) * rs * gg.x + bb.x;
    r.y = (x1 - mean) * rs * gg.y + bb.y;
    r.z = (x2 - mean) * rs * gg.z + bb.z;
    r.w = (x3 - mean) * rs * gg.w + bb.w;
    *(float4*)(out + base + tid * 4) = r;
}

// ---------------- launch ----------------------------------------------------
extern "C" void kernel_launch(void* const* d_in, const int* in_sizes, int n_in,
                              void* d_out, int out_size) {
    const float* x        = (const float*)d_in[0];
    const int*   t_length = (const int*)  d_in[1];
    const int*   rand_idx = (const int*)  d_in[2];
    const float* conv_w   = (const float*)d_in[3];
    const float* bn_g     = (const float*)d_in[4];
    const float* bn_b     = (const float*)d_in[5];
    const float* bn_m     = (const float*)d_in[6];
    const float* bn_v     = (const float*)d_in[7];
    const float* wq = (const float*)d_in[8];  const float* bq = (const float*)d_in[9];
    const float* wk = (const float*)d_in[10]; const float* bk = (const float*)d_in[11];
    const float* wv = (const float*)d_in[12]; const float* bv = (const float*)d_in[13];
    const float* wo = (const float*)d_in[14]; const float* bo = (const float*)d_in[15];
    const float* ln1_g = (const float*)d_in[16]; const float* ln1_b = (const float*)d_in[17];
    const float* w1 = (const float*)d_in[18]; const float* b1 = (const float*)d_in[19];
    const float* w2 = (const float*)d_in[20]; const float* b2 = (const float*)d_in[21];
    const float* ln2_g = (const float*)d_in[22]; const float* ln2_b = (const float*)d_in[23];
    float* out = (float*)d_out;

    static float* p_base = nullptr;
    if (p_base == nullptr) {
        cudaGetSymbolAddress((void**)&p_base, g_scratch);
        cudaFuncSetAttribute((const void*)attn_kernel,
                             cudaFuncAttributeMaxDynamicSharedMemorySize, ATTN_SMEM);
    }
    float* p_xc = p_base;
    float* p_q  = p_base + SEG;       // reused as t1 after attention
    float* p_k  = p_base + SEG * 2;   // reused as h (spans k+v) after attention
    float* p_v  = p_base + SEG * 3;
    float* p_o  = p_base + SEG * 4;
    float* p_x1 = p_base + SEG * 5;
    float* p_t1 = p_q;
    float* p_h  = p_k;

    // 1) conv + residual + BN
    conv_bn_kernel<<<(TBr * Dd) / 256, 256>>>(x, conv_w, bn_g, bn_b, bn_m, bn_v, p_xc);

    // 2) QKV projections (TF32 tensor cores)
    {
        dim3 grid(Dd / 128, TBr / 128);
        mma_gemm_kernel<0><<<grid, 256>>>(TBr, Dd, Dd, p_xc, wq, bq, p_q);
        mma_gemm_kernel<0><<<grid, 256>>>(TBr, Dd, Dd, p_xc, wk, bk, p_k);
        mma_gemm_kernel<0><<<grid, 256>>>(TBr, Dd, Dd, p_xc, wv, bv, p_v);
    }

    // 3) bucketed attention
    {
        dim3 grid(NBn, Hh, Bb);
        attn_kernel<<<grid, 256, ATTN_SMEM>>>(p_q, p_k, p_v, t_length, rand_idx, p_o);
    }

    // 4) O projection
    {
        dim3 grid(Dd / 128, TBr / 128);
        mma_gemm_kernel<0><<<grid, 256>>>(TBr, Dd, Dd, p_o, wo, bo, p_t1);
    }

    // 5) residual + LN1
    res_ln_kernel<<<TBr, 128>>>(p_t1, p_xc, ln1_g, ln1_b, p_x1);

    // 6) MLP up (GeLU fused)
    {
        dim3 grid((2 * Dd) / 128, TBr / 128);
        mma_gemm_kernel<1><<<grid, 256>>>(TBr, 2 * Dd, Dd, p_x1, w1, b1, p_h);
    }

    // 7) MLP down
    {
        dim3 grid(Dd / 128, TBr / 128);
        mma_gemm_kernel<0><<<grid, 256>>>(TBr, Dd, 2 * Dd, p_h, w2, b2, p_t1);
    }

    // 8) residual + LN2 -> output
    res_ln_kernel<<<TBr, 128>>>(p_t1, p_x1, ln2_g, ln2_b, out);
}

// round 7
// speedup vs baseline: 2.6243x; 1.1106x over previous
#include <cuda_runtime.h>
#include <math.h>
#include <stdint.h>

#define Tt  4096
#define Bb  8
#define Dd  512
#define Hh  8
#define NBn 64
#define BSs 64
#define DHh 64
#define TBr (Tt*Bb)          // 32768 rows
#define LNEPS 1e-5f

// ---------------- scratch: single static arena, manually carved -------------
#define SEG ((size_t)TBr * Dd)          // 16,777,216 floats
__device__ float g_scratch[SEG * 6];

// ---------------- conv (depthwise, k=3, pad 1) + residual + BN ---------------
__global__ void conv_bn_kernel(const float* __restrict__ x,
                               const float* __restrict__ w,   // [D,1,3]
                               const float* __restrict__ gg,
                               const float* __restrict__ bb,
                               const float* __restrict__ mm,
                               const float* __restrict__ vv,
                               float* __restrict__ out) {
    int idx = blockIdx.x * blockDim.x + threadIdx.x;
    if (idx >= TBr * Dd) return;
    int d = idx % Dd;
    int t = idx / (Bb * Dd);
    float xm = (t > 0)      ? x[idx - Bb * Dd] : 0.f;
    float xc = x[idx];
    float xp = (t < Tt - 1) ? x[idx + Bb * Dd] : 0.f;
    float y = fmaf(w[d*3+0], xm, fmaf(w[d*3+1], xc, w[d*3+2] * xp)) + xc;
    y = (y - mm[d]) * rsqrtf(vv[d] + LNEPS) * gg[d] + bb[d];
    out[idx] = y;
}

// ---------------- TF32 tensor-core GEMM, cp.async double-buffered ------------
// 128x128x32 CTA tile, 256 threads (8 warps), warp = 32x64, mma.m16n8k8.tf32.
// Dynamic smem: As[2][128][36] + Bs[2][32][136] = 71680 B. 2 CTAs/SM.

__device__ __forceinline__ uint32_t f2tf32(float f) {
    uint32_t r;
    asm("cvt.rna.tf32.f32 %0, %1;" : "=r"(r) : "f"(f));
    return r;
}

__device__ __forceinline__ void mma_tf32(float* d, const uint32_t* a, const uint32_t* b) {
    asm volatile(
        "mma.sync.aligned.m16n8k8.row.col.f32.tf32.tf32.f32 "
        "{%0,%1,%2,%3}, {%4,%5,%6,%7}, {%8,%9}, {%0,%1,%2,%3};\n"
        : "+f"(d[0]), "+f"(d[1]), "+f"(d[2]), "+f"(d[3])
        : "r"(a[0]), "r"(a[1]), "r"(a[2]), "r"(a[3]),
          "r"(b[0]), "r"(b[1]));
}

__device__ __forceinline__ void cp_async16(void* sptr, const void* gptr) {
    uint32_t s = (uint32_t)__cvta_generic_to_shared(sptr);
    asm volatile("cp.async.cg.shared.global [%0], [%1], 16;\n" :: "r"(s), "l"(gptr));
}

#define ASTRIDE 36
#define BSTRIDE 136
#define AST (128 * ASTRIDE)       // floats per A stage
#define BST (32 * BSTRIDE)        // floats per B stage
#define GEMM_SMEM ((2 * AST + 2 * BST) * 4)   // 71680 bytes

template<int GELU>
__global__ void __launch_bounds__(256, 2)
mma_gemm_kernel(int M, int N, int K,
                const float* __restrict__ A, const float* __restrict__ W,
                const float* __restrict__ bias, float* __restrict__ C) {
    extern __shared__ float gsm[];
    float* AsBase = gsm;                 // 2 stages of [128][36]
    float* BsBase = gsm + 2 * AST;       // 2 stages of [32][136]

    const int tid = threadIdx.x;
    const int m0 = blockIdx.y * 128;
    const int n0 = blockIdx.x * 128;
    const int wid  = tid >> 5, lane = tid & 31;
    const int g = lane >> 2, t = lane & 3;
    const int rb = (wid >> 1) * 32;      // warp row base (0..96)
    const int cb = (wid & 1) * 64;       // warp col base (0 or 64)

    // global-load mapping
    const int arow = tid >> 3;           // 0..31 (+i*32)
    const int acol = (tid & 7) * 4;      // 0..28
    const int bkr  = tid >> 5;           // 0..7  (+i*8)
    const int bcol = (tid & 31) * 4;     // 0..124

    float acc[2][8][4];
    #pragma unroll
    for (int mt = 0; mt < 2; mt++)
        #pragma unroll
        for (int nt = 0; nt < 8; nt++)
            #pragma unroll
            for (int c = 0; c < 4; c++) acc[mt][nt][c] = 0.f;

    const int NIT = K / 32;

    // stage-issue lambda (manually inlined twice below)
    // A: rows m0+arow+i*32, cols k0+acol ; B: rows k0+bkr+i*8, cols n0+bcol
    {
        // prologue: stage 0, k0 = 0
        float* As = AsBase;
        float* Bs = BsBase;
        #pragma unroll
        for (int i = 0; i < 4; i++) {
            cp_async16(&As[(arow + i * 32) * ASTRIDE + acol],
                       A + (size_t)(m0 + arow + i * 32) * K + acol);
            cp_async16(&Bs[(bkr + i * 8) * BSTRIDE + bcol],
                       W + (size_t)(bkr + i * 8) * N + n0 + bcol);
        }
        asm volatile("cp.async.commit_group;\n");
    }

    #pragma unroll 1
    for (int it = 0; it < NIT; it++) {
        const int buf = it & 1;
        const bool has_next = (it + 1 < NIT);
        if (has_next) {
            const int k0 = (it + 1) * 32;
            float* As = AsBase + ((it + 1) & 1) * AST;
            float* Bs = BsBase + ((it + 1) & 1) * BST;
            #pragma unroll
            for (int i = 0; i < 4; i++) {
                cp_async16(&As[(arow + i * 32) * ASTRIDE + acol],
                           A + (size_t)(m0 + arow + i * 32) * K + k0 + acol);
                cp_async16(&Bs[(bkr + i * 8) * BSTRIDE + bcol],
                           W + (size_t)(k0 + bkr + i * 8) * N + n0 + bcol);
            }
            asm volatile("cp.async.commit_group;\n");
            asm volatile("cp.async.wait_group 1;\n");
        } else {
            asm volatile("cp.async.wait_group 0;\n");
        }
        __syncthreads();

        const float* Asb = AsBase + buf * AST;
        const float* Bsb = BsBase + buf * BST;
        #pragma unroll
        for (int ks = 0; ks < 4; ks++) {
            const int k8 = ks * 8;
            uint32_t af[2][4];
            #pragma unroll
            for (int mt = 0; mt < 2; mt++) {
                const int r = rb + mt * 16 + g;
                af[mt][0] = f2tf32(Asb[r * ASTRIDE + k8 + t]);
                af[mt][1] = f2tf32(Asb[(r + 8) * ASTRIDE + k8 + t]);
                af[mt][2] = f2tf32(Asb[r * ASTRIDE + k8 + t + 4]);
                af[mt][3] = f2tf32(Asb[(r + 8) * ASTRIDE + k8 + t + 4]);
            }
            uint32_t bf[8][2];
            #pragma unroll
            for (int nt = 0; nt < 8; nt++) {
                const int c = cb + nt * 8 + g;
                bf[nt][0] = f2tf32(Bsb[(k8 + t) * BSTRIDE + c]);
                bf[nt][1] = f2tf32(Bsb[(k8 + t + 4) * BSTRIDE + c]);
            }
            #pragma unroll
            for (int mt = 0; mt < 2; mt++)
                #pragma unroll
                for (int nt = 0; nt < 8; nt++)
                    mma_tf32(acc[mt][nt], af[mt], bf[nt]);
        }
        __syncthreads();
    }

    // epilogue: bias (+ optional exact GeLU), write float2 pairs
    #pragma unroll
    for (int mt = 0; mt < 2; mt++) {
        const int r0 = m0 + rb + mt * 16 + g;
        #pragma unroll
        for (int nt = 0; nt < 8; nt++) {
            const int c = n0 + cb + nt * 8 + 2 * t;
            const float b0 = bias[c], b1 = bias[c + 1];
            float v0 = acc[mt][nt][0] + b0;
            float v1 = acc[mt][nt][1] + b1;
            float v2 = acc[mt][nt][2] + b0;
            float v3 = acc[mt][nt][3] + b1;
            if (GELU) {
                v0 = v0 * 0.5f * (1.f + erff(v0 * 0.70710678118654752f));
                v1 = v1 * 0.5f * (1.f + erff(v1 * 0.70710678118654752f));
                v2 = v2 * 0.5f * (1.f + erff(v2 * 0.70710678118654752f));
                v3 = v3 * 0.5f * (1.f + erff(v3 * 0.70710678118654752f));
            }
            float2 p0; p0.x = v0; p0.y = v1;
            float2 p1; p1.x = v2; p1.y = v3;
            *(float2*)(C + (size_t)r0 * N + c)       = p0;
            *(float2*)(C + (size_t)(r0 + 8) * N + c) = p1;
        }
    }
}

// ---------------- bucketed attention: one CTA per (n, h, b) ------------------
#define ATTN_SMEM ((64*65 + 128*65 + 64*128) * 4)

__global__ void __launch_bounds__(256)
attn_kernel(const float* __restrict__ q, const float* __restrict__ k,
            const float* __restrict__ v, const int* __restrict__ t_len,
            const int* __restrict__ ridx, float* __restrict__ o) {
    const int n = blockIdx.x, h = blockIdx.y, b = blockIdx.z;
    extern __shared__ float sm[];
    float (*Qs)[65]  = (float(*)[65])sm;
    float (*KVs)[65] = (float(*)[65])(sm + 64 * 65);
    float (*Ps)[128] = (float(*)[128])(sm + 64 * 65 + 128 * 65);

    const int tid = threadIdx.x;
    const int tlen = t_len[b];
    const int rn = ridx[n];
    const int chan = h * DHh;

    for (int it = tid; it < 64 * 16; it += 256) {
        int r = it >> 4, c4 = (it & 15) * 4;
        int t = n * BSs + r;
        float4 val = *(const float4*)(q + ((size_t)t * Bb + b) * Dd + chan + c4);
        Qs[r][c4] = val.x; Qs[r][c4+1] = val.y; Qs[r][c4+2] = val.z; Qs[r][c4+3] = val.w;
    }
    for (int it = tid; it < 128 * 16; it += 256) {
        int r = it >> 4, c4 = (it & 15) * 4;
        int t = (r < 64) ? n * BSs + r : rn * BSs + (r - 64);
        float4 val = *(const float4*)(k + ((size_t)t * Bb + b) * Dd + chan + c4);
        KVs[r][c4] = val.x; KVs[r][c4+1] = val.y; KVs[r][c4+2] = val.z; KVs[r][c4+3] = val.w;
    }
    __syncthreads();

    {
        const int i0 = (tid >> 4) * 4;
        const int jl = tid & 15;
        float acc[4][8];
        #pragma unroll
        for (int ii = 0; ii < 4; ii++)
            #pragma unroll
            for (int jj = 0; jj < 8; jj++) acc[ii][jj] = 0.f;

        #pragma unroll 16
        for (int dh = 0; dh < 64; dh++) {
            float qr[4], kr[8];
            #pragma unroll
            for (int ii = 0; ii < 4; ii++) qr[ii] = Qs[i0 + ii][dh];
            #pragma unroll
            for (int jj = 0; jj < 8; jj++) kr[jj] = KVs[jl + jj * 16][dh];
            #pragma unroll
            for (int ii = 0; ii < 4; ii++)
                #pragma unroll
                for (int jj = 0; jj < 8; jj++)
                    acc[ii][jj] = fmaf(qr[ii], kr[jj], acc[ii][jj]);
        }
        #pragma unroll
        for (int jj = 0; jj < 8; jj++) {
            int j = jl + jj * 16;
            int kp = (j < 64) ? n * BSs + j : rn * BSs + (j - 64);
            bool valid = kp < tlen;
            #pragma unroll
            for (int ii = 0; ii < 4; ii++)
                Ps[i0 + ii][j] = valid ? acc[ii][jj] * 0.125f : -1e9f;
        }
    }
    __syncthreads();

    {
        const int warp = tid >> 5, lane = tid & 31;
        for (int r = warp * 8; r < warp * 8 + 8; r++) {
            float v0 = Ps[r][lane], v1 = Ps[r][lane + 32];
            float v2 = Ps[r][lane + 64], v3 = Ps[r][lane + 96];
            float mx = fmaxf(fmaxf(v0, v1), fmaxf(v2, v3));
            #pragma unroll
            for (int off = 16; off; off >>= 1) mx = fmaxf(mx, __shfl_xor_sync(~0u, mx, off));
            v0 = expf(v0 - mx); v1 = expf(v1 - mx);
            v2 = expf(v2 - mx); v3 = expf(v3 - mx);
            float s = v0 + v1 + v2 + v3;
            #pragma unroll
            for (int off = 16; off; off >>= 1) s += __shfl_xor_sync(~0u, s, off);
            float inv = 1.f / s;
            Ps[r][lane]      = v0 * inv;
            Ps[r][lane + 32] = v1 * inv;
            Ps[r][lane + 64] = v2 * inv;
            Ps[r][lane + 96] = v3 * inv;
        }
    }
    __syncthreads();

    for (int it = tid; it < 128 * 16; it += 256) {
        int r = it >> 4, c4 = (it & 15) * 4;
        int t = (r < 64) ? n * BSs + r : rn * BSs + (r - 64);
        float4 val = *(const float4*)(v + ((size_t)t * Bb + b) * Dd + chan + c4);
        KVs[r][c4] = val.x; KVs[r][c4+1] = val.y; KVs[r][c4+2] = val.z; KVs[r][c4+3] = val.w;
    }
    __syncthreads();

    {
        const int i0 = (tid >> 4) * 4;
        const int dh0 = (tid & 15) * 4;
        float acc[4][4];
        #pragma unroll
        for (int ii = 0; ii < 4; ii++)
            #pragma unroll
            for (int c = 0; c < 4; c++) acc[ii][c] = 0.f;

        #pragma unroll 8
        for (int j = 0; j < 128; j++) {
            float pr[4], vr[4];
            #pragma unroll
            for (int ii = 0; ii < 4; ii++) pr[ii] = Ps[i0 + ii][j];
            #pragma unroll
            for (int c = 0; c < 4; c++) vr[c] = KVs[j][dh0 + c];
            #pragma unroll
            for (int ii = 0; ii < 4; ii++)
                #pragma unroll
                for (int c = 0; c < 4; c++)
                    acc[ii][c] = fmaf(pr[ii], vr[c], acc[ii][c]);
        }
        #pragma unroll
        for (int ii = 0; ii < 4; ii++) {
            int t = n * BSs + i0 + ii;
            float4 r;
            r.x = acc[ii][0]; r.y = acc[ii][1]; r.z = acc[ii][2]; r.w = acc[ii][3];
            *(float4*)(o + ((size_t)t * Bb + b) * Dd + chan + dh0) = r;
        }
    }
}

// ---------------- residual + LayerNorm --------------------------------------
__global__ void __launch_bounds__(128)
res_ln_kernel(const float* __restrict__ a, const float* __restrict__ res,
              const float* __restrict__ g, const float* __restrict__ bt,
              float* __restrict__ out) {
    const int row = blockIdx.x;
    const int tid = threadIdx.x;
    const size_t base = (size_t)row * Dd;

    float4 va = *(const float4*)(a   + base + tid * 4);
    float4 vr = *(const float4*)(res + base + tid * 4);
    float x0 = va.x + vr.x, x1 = va.y + vr.y, x2 = va.z + vr.z, x3 = va.w + vr.w;

    float s  = x0 + x1 + x2 + x3;
    float sq = x0*x0 + x1*x1 + x2*x2 + x3*x3;

    const int lane = tid & 31, warp = tid >> 5;
    #pragma unroll
    for (int off = 16; off; off >>= 1) {
        s  += __shfl_xor_sync(~0u, s, off);
        sq += __shfl_xor_sync(~0u, sq, off);
    }
    __shared__ float ss[4], sqs[4];
    if (lane == 0) { ss[warp] = s; sqs[warp] = sq; }
    __syncthreads();
    s  = ss[0] + ss[1] + ss[2] + ss[3];
    sq = sqs[0] + sqs[1] + sqs[2] + sqs[3];

    float mean = s * (1.f / Dd);
    float var  = sq * (1.f / Dd) - mean * mean;
    float rs   = rsqrtf(var + LNEPS);

    float4 gg = *(const float4*)(g  + tid * 4);
    float4 bb = *(const float4*)(bt + tid * 4);
    float4 r;
    r.x = (x0 - mean) * rs * gg.x + bb.x;
    r.y = (x1 - mean) * rs * gg.y + bb.y;
    r.z = (x2 - mean) * rs * gg.z + bb.z;
    r.w = (x3 - mean) * rs * gg.w + bb.w;
    *(float4*)(out + base + tid * 4) = r;
}

// ---------------- launch ----------------------------------------------------
extern "C" void kernel_launch(void* const* d_in, const int* in_sizes, int n_in,
                              void* d_out, int out_size) {
    const float* x        = (const float*)d_in[0];
    const int*   t_length = (const int*)  d_in[1];
    const int*   rand_idx = (const int*)  d_in[2];
    const float* conv_w   = (const float*)d_in[3];
    const float* bn_g     = (const float*)d_in[4];
    const float* bn_b     = (const float*)d_in[5];
    const float* bn_m     = (const float*)d_in[6];
    const float* bn_v     = (const float*)d_in[7];
    const float* wq = (const float*)d_in[8];  const float* bq = (const float*)d_in[9];
    const float* wk = (const float*)d_in[10]; const float* bk = (const float*)d_in[11];
    const float* wv = (const float*)d_in[12]; const float* bv = (const float*)d_in[13];
    const float* wo = (const float*)d_in[14]; const float* bo = (const float*)d_in[15];
    const float* ln1_g = (const float*)d_in[16]; const float* ln1_b = (const float*)d_in[17];
    const float* w1 = (const float*)d_in[18]; const float* b1 = (const float*)d_in[19];
    const float* w2 = (const float*)d_in[20]; const float* b2 = (const float*)d_in[21];
    const float* ln2_g = (const float*)d_in[22]; const float* ln2_b = (const float*)d_in[23];
    float* out = (float*)d_out;

    static float* p_base = nullptr;
    if (p_base == nullptr) {
        cudaGetSymbolAddress((void**)&p_base, g_scratch);
        cudaFuncSetAttribute((const void*)attn_kernel,
                             cudaFuncAttributeMaxDynamicSharedMemorySize, ATTN_SMEM);
        cudaFuncSetAttribute((const void*)mma_gemm_kernel<0>,
                             cudaFuncAttributeMaxDynamicSharedMemorySize, GEMM_SMEM);
        cudaFuncSetAttribute((const void*)mma_gemm_kernel<1>,
                             cudaFuncAttributeMaxDynamicSharedMemorySize, GEMM_SMEM);
    }
    float* p_xc = p_base;
    float* p_q  = p_base + SEG;       // reused as t1 after attention
    float* p_k  = p_base + SEG * 2;   // reused as h (spans k+v) after attention
    float* p_v  = p_base + SEG * 3;
    float* p_o  = p_base + SEG * 4;
    float* p_x1 = p_base + SEG * 5;
    float* p_t1 = p_q;
    float* p_h  = p_k;

    // 1) conv + residual + BN
    conv_bn_kernel<<<(TBr * Dd) / 256, 256>>>(x, conv_w, bn_g, bn_b, bn_m, bn_v, p_xc);

    // 2) QKV projections (TF32 tensor cores, cp.async pipeline)
    {
        dim3 grid(Dd / 128, TBr / 128);
        mma_gemm_kernel<0><<<grid, 256, GEMM_SMEM>>>(TBr, Dd, Dd, p_xc, wq, bq, p_q);
        mma_gemm_kernel<0><<<grid, 256, GEMM_SMEM>>>(TBr, Dd, Dd, p_xc, wk, bk, p_k);
        mma_gemm_kernel<0><<<grid, 256, GEMM_SMEM>>>(TBr, Dd, Dd, p_xc, wv, bv, p_v);
    }

    // 3) bucketed attention
    {
        dim3 grid(NBn, Hh, Bb);
        attn_kernel<<<grid, 256, ATTN_SMEM>>>(p_q, p_k, p_v, t_length, rand_idx, p_o);
    }

    // 4) O projection
    {
        dim3 grid(Dd / 128, TBr / 128);
        mma_gemm_kernel<0><<<grid, 256, GEMM_SMEM>>>(TBr, Dd, Dd, p_o, wo, bo, p_t1);
    }

    // 5) residual + LN1
    res_ln_kernel<<<TBr, 128>>>(p_t1, p_xc, ln1_g, ln1_b, p_x1);

    // 6) MLP up (GeLU fused)
    {
        dim3 grid((2 * Dd) / 128, TBr / 128);
        mma_gemm_kernel<1><<<grid, 256, GEMM_SMEM>>>(TBr, 2 * Dd, Dd, p_x1, w1, b1, p_h);
    }

    // 7) MLP down
    {
        dim3 grid(Dd / 128, TBr / 128);
        mma_gemm_kernel<0><<<grid, 256, GEMM_SMEM>>>(TBr, Dd, 2 * Dd, p_h, w2, b2, p_t1);
    }

    // 8) residual + LN2 -> output
    res_ln_kernel<<<TBr, 128>>>(p_t1, p_x1, ln2_g, ln2_b, out);
}

// round 8
// speedup vs baseline: 2.8389x; 1.0818x over previous
#include <cuda_runtime.h>
#include <math.h>
#include <stdint.h>

#define Tt  4096
#define Bb  8
#define Dd  512
#define Hh  8
#define NBn 64
#define BSs 64
#define DHh 64
#define TBr (Tt*Bb)          // 32768 rows
#define LNEPS 1e-5f

// ---------------- scratch: single static arena, manually carved -------------
#define SEG ((size_t)TBr * Dd)          // 16,777,216 floats
__device__ float g_scratch[SEG * 6];

// ---------------- conv (depthwise, k=3, pad 1) + residual + BN ---------------
__global__ void conv_bn_kernel(const float* __restrict__ x,
                               const float* __restrict__ w,   // [D,1,3]
                               const float* __restrict__ gg,
                               const float* __restrict__ bb,
                               const float* __restrict__ mm,
                               const float* __restrict__ vv,
                               float* __restrict__ out) {
    int idx = blockIdx.x * blockDim.x + threadIdx.x;
    if (idx >= TBr * Dd) return;
    int d = idx % Dd;
    int t = idx / (Bb * Dd);
    float xm = (t > 0)      ? x[idx - Bb * Dd] : 0.f;
    float xc = x[idx];
    float xp = (t < Tt - 1) ? x[idx + Bb * Dd] : 0.f;
    float y = fmaf(w[d*3+0], xm, fmaf(w[d*3+1], xc, w[d*3+2] * xp)) + xc;
    y = (y - mm[d]) * rsqrtf(vv[d] + LNEPS) * gg[d] + bb[d];
    out[idx] = y;
}

// ---------------- TF32 tensor-core GEMM, 3-stage cp.async pipeline -----------
// 128x128x32 CTA tile, 256 threads (8 warps), warp = 32x64, mma.m16n8k8.tf32.
// fp32 bits fed directly to tf32 mma (HW truncates mantissa; no cvt in loop).
// Dynamic smem: 3 stages x (As[128][36] + Bs[32][136]) = 107,520 B. 2 CTAs/SM.

__device__ __forceinline__ void mma_tf32(float* d, const uint32_t* a, const uint32_t* b) {
    asm volatile(
        "mma.sync.aligned.m16n8k8.row.col.f32.tf32.tf32.f32 "
        "{%0,%1,%2,%3}, {%4,%5,%6,%7}, {%8,%9}, {%0,%1,%2,%3};\n"
        : "+f"(d[0]), "+f"(d[1]), "+f"(d[2]), "+f"(d[3])
        : "r"(a[0]), "r"(a[1]), "r"(a[2]), "r"(a[3]),
          "r"(b[0]), "r"(b[1]));
}

__device__ __forceinline__ void cp_async16(void* sptr, const void* gptr) {
    uint32_t s = (uint32_t)__cvta_generic_to_shared(sptr);
    asm volatile("cp.async.cg.shared.global [%0], [%1], 16;\n" :: "r"(s), "l"(gptr));
}

#define ASTRIDE 36
#define BSTRIDE 136
#define AST (128 * ASTRIDE)       // floats per A stage (4608)
#define BST (32 * BSTRIDE)        // floats per B stage (4352)
#define STG (AST + BST)           // floats per full stage (8960)
#define GEMM_SMEM (3 * STG * 4)   // 107,520 bytes

template<int GELU>
__global__ void __launch_bounds__(256, 2)
mma_gemm_kernel(int M, int N, int K,
                const float* __restrict__ A, const float* __restrict__ W,
                const float* __restrict__ bias, float* __restrict__ C) {
    extern __shared__ float gsm[];   // 3 stages: [As | Bs] each

    const int tid = threadIdx.x;
    const int m0 = blockIdx.y * 128;
    const int n0 = blockIdx.x * 128;
    const int wid  = tid >> 5, lane = tid & 31;
    const int g = lane >> 2, t = lane & 3;
    const int rb = (wid >> 1) * 32;      // warp row base (0..96)
    const int cb = (wid & 1) * 64;       // warp col base (0 or 64)

    // global-load mapping
    const int arow = tid >> 3;           // 0..31 (+i*32)
    const int acol = (tid & 7) * 4;      // 0..28
    const int bkr  = tid >> 5;           // 0..7  (+i*8)
    const int bcol = (tid & 31) * 4;     // 0..124

    float acc[2][8][4];
    #pragma unroll
    for (int mt = 0; mt < 2; mt++)
        #pragma unroll
        for (int nt = 0; nt < 8; nt++)
            #pragma unroll
            for (int c = 0; c < 4; c++) acc[mt][nt][c] = 0.f;

    const int NIT = K / 32;

    // prologue: issue stages 0 and 1
    #pragma unroll
    for (int s = 0; s < 2; s++) {
        float* As = gsm + s * STG;
        float* Bs = As + AST;
        const int k0 = s * 32;
        #pragma unroll
        for (int i = 0; i < 4; i++) {
            cp_async16(&As[(arow + i * 32) * ASTRIDE + acol],
                       A + (size_t)(m0 + arow + i * 32) * K + k0 + acol);
            cp_async16(&Bs[(bkr + i * 8) * BSTRIDE + bcol],
                       W + (size_t)(k0 + bkr + i * 8) * N + n0 + bcol);
        }
        asm volatile("cp.async.commit_group;\n");
    }

    int slot = 0;          // slot of stage `it`
    int nslot = 2;         // slot for stage `it+2`
    #pragma unroll 1
    for (int it = 0; it < NIT; it++) {
        const bool more = (it + 2 < NIT);
        if (more) { asm volatile("cp.async.wait_group 1;\n"); }
        else      { asm volatile("cp.async.wait_group 0;\n"); }
        __syncthreads();   // stage `it` ready AND all warps done with slot `nslot`'s old data

        if (more) {
            float* As = gsm + nslot * STG;
            float* Bs = As + AST;
            const int k0 = (it + 2) * 32;
            #pragma unroll
            for (int i = 0; i < 4; i++) {
                cp_async16(&As[(arow + i * 32) * ASTRIDE + acol],
                           A + (size_t)(m0 + arow + i * 32) * K + k0 + acol);
                cp_async16(&Bs[(bkr + i * 8) * BSTRIDE + bcol],
                           W + (size_t)(k0 + bkr + i * 8) * N + n0 + bcol);
            }
            asm volatile("cp.async.commit_group;\n");
        }

        const float* Asb = gsm + slot * STG;
        const float* Bsb = Asb + AST;
        #pragma unroll
        for (int ks = 0; ks < 4; ks++) {
            const int k8 = ks * 8;
            uint32_t af[2][4];
            #pragma unroll
            for (int mt = 0; mt < 2; mt++) {
                const int r = rb + mt * 16 + g;
                af[mt][0] = __float_as_uint(Asb[r * ASTRIDE + k8 + t]);
                af[mt][1] = __float_as_uint(Asb[(r + 8) * ASTRIDE + k8 + t]);
                af[mt][2] = __float_as_uint(Asb[r * ASTRIDE + k8 + t + 4]);
                af[mt][3] = __float_as_uint(Asb[(r + 8) * ASTRIDE + k8 + t + 4]);
            }
            uint32_t bf[8][2];
            #pragma unroll
            for (int nt = 0; nt < 8; nt++) {
                const int c = cb + nt * 8 + g;
                bf[nt][0] = __float_as_uint(Bsb[(k8 + t) * BSTRIDE + c]);
                bf[nt][1] = __float_as_uint(Bsb[(k8 + t + 4) * BSTRIDE + c]);
            }
            #pragma unroll
            for (int mt = 0; mt < 2; mt++)
                #pragma unroll
                for (int nt = 0; nt < 8; nt++)
                    mma_tf32(acc[mt][nt], af[mt], bf[nt]);
        }

        slot = (slot + 1 == 3) ? 0 : slot + 1;
        nslot = (nslot + 1 == 3) ? 0 : nslot + 1;
    }

    // epilogue: bias (+ optional exact GeLU), write float2 pairs
    #pragma unroll
    for (int mt = 0; mt < 2; mt++) {
        const int r0 = m0 + rb + mt * 16 + g;
        #pragma unroll
        for (int nt = 0; nt < 8; nt++) {
            const int c = n0 + cb + nt * 8 + 2 * t;
            const float b0 = bias[c], b1 = bias[c + 1];
            float v0 = acc[mt][nt][0] + b0;
            float v1 = acc[mt][nt][1] + b1;
            float v2 = acc[mt][nt][2] + b0;
            float v3 = acc[mt][nt][3] + b1;
            if (GELU) {
                v0 = v0 * 0.5f * (1.f + erff(v0 * 0.70710678118654752f));
                v1 = v1 * 0.5f * (1.f + erff(v1 * 0.70710678118654752f));
                v2 = v2 * 0.5f * (1.f + erff(v2 * 0.70710678118654752f));
                v3 = v3 * 0.5f * (1.f + erff(v3 * 0.70710678118654752f));
            }
            float2 p0; p0.x = v0; p0.y = v1;
            float2 p1; p1.x = v2; p1.y = v3;
            *(float2*)(C + (size_t)r0 * N + c)       = p0;
            *(float2*)(C + (size_t)(r0 + 8) * N + c) = p1;
        }
    }
}

// ---------------- bucketed attention: one CTA per (n, h, b) ------------------
#define ATTN_SMEM ((64*65 + 128*65 + 64*128) * 4)

__global__ void __launch_bounds__(256)
attn_kernel(const float* __restrict__ q, const float* __restrict__ k,
            const float* __restrict__ v, const int* __restrict__ t_len,
            const int* __restrict__ ridx, float* __restrict__ o) {
    const int n = blockIdx.x, h = blockIdx.y, b = blockIdx.z;
    extern __shared__ float sm[];
    float (*Qs)[65]  = (float(*)[65])sm;
    float (*KVs)[65] = (float(*)[65])(sm + 64 * 65);
    float (*Ps)[128] = (float(*)[128])(sm + 64 * 65 + 128 * 65);

    const int tid = threadIdx.x;
    const int tlen = t_len[b];
    const int rn = ridx[n];
    const int chan = h * DHh;

    for (int it = tid; it < 64 * 16; it += 256) {
        int r = it >> 4, c4 = (it & 15) * 4;
        int t = n * BSs + r;
        float4 val = *(const float4*)(q + ((size_t)t * Bb + b) * Dd + chan + c4);
        Qs[r][c4] = val.x; Qs[r][c4+1] = val.y; Qs[r][c4+2] = val.z; Qs[r][c4+3] = val.w;
    }
    for (int it = tid; it < 128 * 16; it += 256) {
        int r = it >> 4, c4 = (it & 15) * 4;
        int t = (r < 64) ? n * BSs + r : rn * BSs + (r - 64);
        float4 val = *(const float4*)(k + ((size_t)t * Bb + b) * Dd + chan + c4);
        KVs[r][c4] = val.x; KVs[r][c4+1] = val.y; KVs[r][c4+2] = val.z; KVs[r][c4+3] = val.w;
    }
    __syncthreads();

    {
        const int i0 = (tid >> 4) * 4;
        const int jl = tid & 15;
        float acc[4][8];
        #pragma unroll
        for (int ii = 0; ii < 4; ii++)
            #pragma unroll
            for (int jj = 0; jj < 8; jj++) acc[ii][jj] = 0.f;

        #pragma unroll 16
        for (int dh = 0; dh < 64; dh++) {
            float qr[4], kr[8];
            #pragma unroll
            for (int ii = 0; ii < 4; ii++) qr[ii] = Qs[i0 + ii][dh];
            #pragma unroll
            for (int jj = 0; jj < 8; jj++) kr[jj] = KVs[jl + jj * 16][dh];
            #pragma unroll
            for (int ii = 0; ii < 4; ii++)
                #pragma unroll
                for (int jj = 0; jj < 8; jj++)
                    acc[ii][jj] = fmaf(qr[ii], kr[jj], acc[ii][jj]);
        }
        #pragma unroll
        for (int jj = 0; jj < 8; jj++) {
            int j = jl + jj * 16;
            int kp = (j < 64) ? n * BSs + j : rn * BSs + (j - 64);
            bool valid = kp < tlen;
            #pragma unroll
            for (int ii = 0; ii < 4; ii++)
                Ps[i0 + ii][j] = valid ? acc[ii][jj] * 0.125f : -1e9f;
        }
    }
    __syncthreads();

    {
        const int warp = tid >> 5, lane = tid & 31;
        for (int r = warp * 8; r < warp * 8 + 8; r++) {
            float v0 = Ps[r][lane], v1 = Ps[r][lane + 32];
            float v2 = Ps[r][lane + 64], v3 = Ps[r][lane + 96];
            float mx = fmaxf(fmaxf(v0, v1), fmaxf(v2, v3));
            #pragma unroll
            for (int off = 16; off; off >>= 1) mx = fmaxf(mx, __shfl_xor_sync(~0u, mx, off));
            v0 = expf(v0 - mx); v1 = expf(v1 - mx);
            v2 = expf(v2 - mx); v3 = expf(v3 - mx);
            float s = v0 + v1 + v2 + v3;
            #pragma unroll
            for (int off = 16; off; off >>= 1) s += __shfl_xor_sync(~0u, s, off);
            float inv = 1.f / s;
            Ps[r][lane]      = v0 * inv;
            Ps[r][lane + 32] = v1 * inv;
            Ps[r][lane + 64] = v2 * inv;
            Ps[r][lane + 96] = v3 * inv;
        }
    }
    __syncthreads();

    for (int it = tid; it < 128 * 16; it += 256) {
        int r = it >> 4, c4 = (it & 15) * 4;
        int t = (r < 64) ? n * BSs + r : rn * BSs + (r - 64);
        float4 val = *(const float4*)(v + ((size_t)t * Bb + b) * Dd + chan + c4);
        KVs[r][c4] = val.x; KVs[r][c4+1] = val.y; KVs[r][c4+2] = val.z; KVs[r][c4+3] = val.w;
    }
    __syncthreads();

    {
        const int i0 = (tid >> 4) * 4;
        const int dh0 = (tid & 15) * 4;
        float acc[4][4];
        #pragma unroll
        for (int ii = 0; ii < 4; ii++)
            #pragma unroll
            for (int c = 0; c < 4; c++) acc[ii][c] = 0.f;

        #pragma unroll 8
        for (int j = 0; j < 128; j++) {
            float pr[4], vr[4];
            #pragma unroll
            for (int ii = 0; ii < 4; ii++) pr[ii] = Ps[i0 + ii][j];
            #pragma unroll
            for (int c = 0; c < 4; c++) vr[c] = KVs[j][dh0 + c];
            #pragma unroll
            for (int ii = 0; ii < 4; ii++)
                #pragma unroll
                for (int c = 0; c < 4; c++)
                    acc[ii][c] = fmaf(pr[ii], vr[c], acc[ii][c]);
        }
        #pragma unroll
        for (int ii = 0; ii < 4; ii++) {
            int t = n * BSs + i0 + ii;
            float4 r;
            r.x = acc[ii][0]; r.y = acc[ii][1]; r.z = acc[ii][2]; r.w = acc[ii][3];
            *(float4*)(o + ((size_t)t * Bb + b) * Dd + chan + dh0) = r;
        }
    }
}

// ---------------- residual + LayerNorm --------------------------------------
__global__ void __launch_bounds__(128)
res_ln_kernel(const float* __restrict__ a, const float* __restrict__ res,
              const float* __restrict__ g, const float* __restrict__ bt,
              float* __restrict__ out) {
    const int row = blockIdx.x;
    const int tid = threadIdx.x;
    const size_t base = (size_t)row * Dd;

    float4 va = *(const float4*)(a   + base + tid * 4);
    float4 vr = *(const float4*)(res + base + tid * 4);
    float x0 = va.x + vr.x, x1 = va.y + vr.y, x2 = va.z + vr.z, x3 = va.w + vr.w;

    float s  = x0 + x1 + x2 + x3;
    float sq = x0*x0 + x1*x1 + x2*x2 + x3*x3;

    const int lane = tid & 31, warp = tid >> 5;
    #pragma unroll
    for (int off = 16; off; off >>= 1) {
        s  += __shfl_xor_sync(~0u, s, off);
        sq += __shfl_xor_sync(~0u, sq, off);
    }
    __shared__ float ss[4], sqs[4];
    if (lane == 0) { ss[warp] = s; sqs[warp] = sq; }
    __syncthreads();
    s  = ss[0] + ss[1] + ss[2] + ss[3];
    sq = sqs[0] + sqs[1] + sqs[2] + sqs[3];

    float mean = s * (1.f / Dd);
    float var  = sq * (1.f / Dd) - mean * mean;
    float rs   = rsqrtf(var + LNEPS);

    float4 gg = *(const float4*)(g  + tid * 4);
    float4 bb = *(const float4*)(bt + tid * 4);
    float4 r;
    r.x = (x0 - mean) * rs * gg.x + bb.x;
    r.y = (x1 - mean) * rs * gg.y + bb.y;
    r.z = (x2 - mean) * rs * gg.z + bb.z;
    r.w = (x3 - mean) * rs * gg.w + bb.w;
    *(float4*)(out + base + tid * 4) = r;
}

// ---------------- launch ----------------------------------------------------
extern "C" void kernel_launch(void* const* d_in, const int* in_sizes, int n_in,
                              void* d_out, int out_size) {
    const float* x        = (const float*)d_in[0];
    const int*   t_length = (const int*)  d_in[1];
    const int*   rand_idx = (const int*)  d_in[2];
    const float* conv_w   = (const float*)d_in[3];
    const float* bn_g     = (const float*)d_in[4];
    const float* bn_b     = (const float*)d_in[5];
    const float* bn_m     = (const float*)d_in[6];
    const float* bn_v     = (const float*)d_in[7];
    const float* wq = (const float*)d_in[8];  const float* bq = (const float*)d_in[9];
    const float* wk = (const float*)d_in[10]; const float* bk = (const float*)d_in[11];
    const float* wv = (const float*)d_in[12]; const float* bv = (const float*)d_in[13];
    const float* wo = (const float*)d_in[14]; const float* bo = (const float*)d_in[15];
    const float* ln1_g = (const float*)d_in[16]; const float* ln1_b = (const float*)d_in[17];
    const float* w1 = (const float*)d_in[18]; const float* b1 = (const float*)d_in[19];
    const float* w2 = (const float*)d_in[20]; const float* b2 = (const float*)d_in[21];
    const float* ln2_g = (const float*)d_in[22]; const float* ln2_b = (const float*)d_in[23];
    float* out = (float*)d_out;

    static float* p_base = nullptr;
    if (p_base == nullptr) {
        cudaGetSymbolAddress((void**)&p_base, g_scratch);
        cudaFuncSetAttribute((const void*)attn_kernel,
                             cudaFuncAttributeMaxDynamicSharedMemorySize, ATTN_SMEM);
        cudaFuncSetAttribute((const void*)mma_gemm_kernel<0>,
                             cudaFuncAttributeMaxDynamicSharedMemorySize, GEMM_SMEM);
        cudaFuncSetAttribute((const void*)mma_gemm_kernel<1>,
                             cudaFuncAttributeMaxDynamicSharedMemorySize, GEMM_SMEM);
    }
    float* p_xc = p_base;
    float* p_q  = p_base + SEG;       // reused as t1 after attention
    float* p_k  = p_base + SEG * 2;   // reused as h (spans k+v) after attention
    float* p_v  = p_base + SEG * 3;
    float* p_o  = p_base + SEG * 4;
    float* p_x1 = p_base + SEG * 5;
    float* p_t1 = p_q;
    float* p_h  = p_k;

    // 1) conv + residual + BN
    conv_bn_kernel<<<(TBr * Dd) / 256, 256>>>(x, conv_w, bn_g, bn_b, bn_m, bn_v, p_xc);

    // 2) QKV projections (TF32 tensor cores, 3-stage cp.async pipeline)
    {
        dim3 grid(Dd / 128, TBr / 128);
        mma_gemm_kernel<0><<<grid, 256, GEMM_SMEM>>>(TBr, Dd, Dd, p_xc, wq, bq, p_q);
        mma_gemm_kernel<0><<<grid, 256, GEMM_SMEM>>>(TBr, Dd, Dd, p_xc, wk, bk, p_k);
        mma_gemm_kernel<0><<<grid, 256, GEMM_SMEM>>>(TBr, Dd, Dd, p_xc, wv, bv, p_v);
    }

    // 3) bucketed attention
    {
        dim3 grid(NBn, Hh, Bb);
        attn_kernel<<<grid, 256, ATTN_SMEM>>>(p_q, p_k, p_v, t_length, rand_idx, p_o);
    }

    // 4) O projection
    {
        dim3 grid(Dd / 128, TBr / 128);
        mma_gemm_kernel<0><<<grid, 256, GEMM_SMEM>>>(TBr, Dd, Dd, p_o, wo, bo, p_t1);
    }

    // 5) residual + LN1
    res_ln_kernel<<<TBr, 128>>>(p_t1, p_xc, ln1_g, ln1_b, p_x1);

    // 6) MLP up (GeLU fused)
    {
        dim3 grid((2 * Dd) / 128, TBr / 128);
        mma_gemm_kernel<1><<<grid, 256, GEMM_SMEM>>>(TBr, 2 * Dd, Dd, p_x1, w1, b1, p_h);
    }

    // 7) MLP down
    {
        dim3 grid(Dd / 128, TBr / 128);
        mma_gemm_kernel<0><<<grid, 256, GEMM_SMEM>>>(TBr, Dd, 2 * Dd, p_h, w2, b2, p_t1);
    }

    // 8) residual + LN2 -> output
    res_ln_kernel<<<TBr, 128>>>(p_t1, p_x1, ln2_g, ln2_b, out);
}

// round 9
// speedup vs baseline: 2.9955x; 1.0551x over previous
#include <cuda_runtime.h>
#include <math.h>
#include <stdint.h>

#define Tt  4096
#define Bb  8
#define Dd  512
#define Hh  8
#define NBn 64
#define BSs 64
#define DHh 64
#define TBr (Tt*Bb)          // 32768 rows
#define LNEPS 1e-5f

// ---------------- scratch: single static arena, manually carved -------------
#define SEG ((size_t)TBr * Dd)          // 16,777,216 floats
__device__ float g_scratch[SEG * 6];

// ---------------- conv (depthwise, k=3, pad 1) + residual + BN ---------------
__global__ void conv_bn_kernel(const float* __restrict__ x,
                               const float* __restrict__ w,   // [D,1,3]
                               const float* __restrict__ gg,
                               const float* __restrict__ bb,
                               const float* __restrict__ mm,
                               const float* __restrict__ vv,
                               float* __restrict__ out) {
    int idx = blockIdx.x * blockDim.x + threadIdx.x;
    if (idx >= TBr * Dd) return;
    int d = idx % Dd;
    int t = idx / (Bb * Dd);
    float xm = (t > 0)      ? x[idx - Bb * Dd] : 0.f;
    float xc = x[idx];
    float xp = (t < Tt - 1) ? x[idx + Bb * Dd] : 0.f;
    float y = fmaf(w[d*3+0], xm, fmaf(w[d*3+1], xc, w[d*3+2] * xp)) + xc;
    y = (y - mm[d]) * rsqrtf(vv[d] + LNEPS) * gg[d] + bb[d];
    out[idx] = y;
}

// ---------------- shared MMA helpers -----------------------------------------
__device__ __forceinline__ void mma_tf32(float* d, const uint32_t* a, const uint32_t* b) {
    asm volatile(
        "mma.sync.aligned.m16n8k8.row.col.f32.tf32.tf32.f32 "
        "{%0,%1,%2,%3}, {%4,%5,%6,%7}, {%8,%9}, {%0,%1,%2,%3};\n"
        : "+f"(d[0]), "+f"(d[1]), "+f"(d[2]), "+f"(d[3])
        : "r"(a[0]), "r"(a[1]), "r"(a[2]), "r"(a[3]),
          "r"(b[0]), "r"(b[1]));
}

__device__ __forceinline__ void cp_async16(void* sptr, const void* gptr) {
    uint32_t s = (uint32_t)__cvta_generic_to_shared(sptr);
    asm volatile("cp.async.cg.shared.global [%0], [%1], 16;\n" :: "r"(s), "l"(gptr));
}

// ---------------- TF32 tensor-core GEMM, 3-stage cp.async pipeline -----------
#define ASTRIDE 36
#define BSTRIDE 136
#define AST (128 * ASTRIDE)
#define BST (32 * BSTRIDE)
#define STG (AST + BST)
#define GEMM_SMEM (3 * STG * 4)   // 107,520 bytes

template<int GELU>
__global__ void __launch_bounds__(256, 2)
mma_gemm_kernel(int M, int N, int K,
                const float* __restrict__ A, const float* __restrict__ W,
                const float* __restrict__ bias, float* __restrict__ C) {
    extern __shared__ float gsm[];

    const int tid = threadIdx.x;
    const int m0 = blockIdx.y * 128;
    const int n0 = blockIdx.x * 128;
    const int wid  = tid >> 5, lane = tid & 31;
    const int g = lane >> 2, t = lane & 3;
    const int rb = (wid >> 1) * 32;
    const int cb = (wid & 1) * 64;

    const int arow = tid >> 3;
    const int acol = (tid & 7) * 4;
    const int bkr  = tid >> 5;
    const int bcol = (tid & 31) * 4;

    float acc[2][8][4];
    #pragma unroll
    for (int mt = 0; mt < 2; mt++)
        #pragma unroll
        for (int nt = 0; nt < 8; nt++)
            #pragma unroll
            for (int c = 0; c < 4; c++) acc[mt][nt][c] = 0.f;

    const int NIT = K / 32;

    #pragma unroll
    for (int s = 0; s < 2; s++) {
        float* As = gsm + s * STG;
        float* Bs = As + AST;
        const int k0 = s * 32;
        #pragma unroll
        for (int i = 0; i < 4; i++) {
            cp_async16(&As[(arow + i * 32) * ASTRIDE + acol],
                       A + (size_t)(m0 + arow + i * 32) * K + k0 + acol);
            cp_async16(&Bs[(bkr + i * 8) * BSTRIDE + bcol],
                       W + (size_t)(k0 + bkr + i * 8) * N + n0 + bcol);
        }
        asm volatile("cp.async.commit_group;\n");
    }

    int slot = 0, nslot = 2;
    #pragma unroll 1
    for (int it = 0; it < NIT; it++) {
        const bool more = (it + 2 < NIT);
        if (more) { asm volatile("cp.async.wait_group 1;\n"); }
        else      { asm volatile("cp.async.wait_group 0;\n"); }
        __syncthreads();

        if (more) {
            float* As = gsm + nslot * STG;
            float* Bs = As + AST;
            const int k0 = (it + 2) * 32;
            #pragma unroll
            for (int i = 0; i < 4; i++) {
                cp_async16(&As[(arow + i * 32) * ASTRIDE + acol],
                           A + (size_t)(m0 + arow + i * 32) * K + k0 + acol);
                cp_async16(&Bs[(bkr + i * 8) * BSTRIDE + bcol],
                           W + (size_t)(k0 + bkr + i * 8) * N + n0 + bcol);
            }
            asm volatile("cp.async.commit_group;\n");
        }

        const float* Asb = gsm + slot * STG;
        const float* Bsb = Asb + AST;
        #pragma unroll
        for (int ks = 0; ks < 4; ks++) {
            const int k8 = ks * 8;
            uint32_t af[2][4];
            #pragma unroll
            for (int mt = 0; mt < 2; mt++) {
                const int r = rb + mt * 16 + g;
                af[mt][0] = __float_as_uint(Asb[r * ASTRIDE + k8 + t]);
                af[mt][1] = __float_as_uint(Asb[(r + 8) * ASTRIDE + k8 + t]);
                af[mt][2] = __float_as_uint(Asb[r * ASTRIDE + k8 + t + 4]);
                af[mt][3] = __float_as_uint(Asb[(r + 8) * ASTRIDE + k8 + t + 4]);
            }
            uint32_t bf[8][2];
            #pragma unroll
            for (int nt = 0; nt < 8; nt++) {
                const int c = cb + nt * 8 + g;
                bf[nt][0] = __float_as_uint(Bsb[(k8 + t) * BSTRIDE + c]);
                bf[nt][1] = __float_as_uint(Bsb[(k8 + t + 4) * BSTRIDE + c]);
            }
            #pragma unroll
            for (int mt = 0; mt < 2; mt++)
                #pragma unroll
                for (int nt = 0; nt < 8; nt++)
                    mma_tf32(acc[mt][nt], af[mt], bf[nt]);
        }

        slot = (slot + 1 == 3) ? 0 : slot + 1;
        nslot = (nslot + 1 == 3) ? 0 : nslot + 1;
    }

    #pragma unroll
    for (int mt = 0; mt < 2; mt++) {
        const int r0 = m0 + rb + mt * 16 + g;
        #pragma unroll
        for (int nt = 0; nt < 8; nt++) {
            const int c = n0 + cb + nt * 8 + 2 * t;
            const float b0 = bias[c], b1 = bias[c + 1];
            float v0 = acc[mt][nt][0] + b0;
            float v1 = acc[mt][nt][1] + b1;
            float v2 = acc[mt][nt][2] + b0;
            float v3 = acc[mt][nt][3] + b1;
            if (GELU) {
                v0 = v0 * 0.5f * (1.f + erff(v0 * 0.70710678118654752f));
                v1 = v1 * 0.5f * (1.f + erff(v1 * 0.70710678118654752f));
                v2 = v2 * 0.5f * (1.f + erff(v2 * 0.70710678118654752f));
                v3 = v3 * 0.5f * (1.f + erff(v3 * 0.70710678118654752f));
            }
            float2 p0; p0.x = v0; p0.y = v1;
            float2 p1; p1.x = v2; p1.y = v3;
            *(float2*)(C + (size_t)r0 * N + c)       = p0;
            *(float2*)(C + (size_t)(r0 + 8) * N + c) = p1;
        }
    }
}

// ---------------- bucketed attention, tensor-core version --------------------
// One CTA per (n, h, b). 256 threads = 8 warps.
// S-phase:  warp = (m-tile mw=wid>>1 of 4) x (64-col half=wid&1)
// O-phase:  warp = m-tile x (32-col half)
#define QS_STRIDE 68     // mod 32 = 4 -> A-frag loads conflict-free
#define KS_STRIDE 68     // row-indexed by g  -> 4g+t distinct
#define VS_STRIDE 72     // row-indexed by t  -> 8t+g distinct
#define PS_STRIDE 132    // mod 32 = 4
#define SM_QS 0
#define SM_KS (64 * QS_STRIDE)                 // 4352
#define SM_VS (SM_KS + 128 * KS_STRIDE)        // 13056
#define SM_PS (SM_VS + 128 * VS_STRIDE)        // 22272
#define SM_MAX (SM_PS + 64 * PS_STRIDE)        // 30720 : [2][64]
#define SM_SUM (SM_MAX + 128)                  // 30848 : [2][64]
#define ATTN_SMEM ((SM_SUM + 128) * 4)         // 123,904 bytes

__global__ void __launch_bounds__(256)
attn_kernel(const float* __restrict__ q, const float* __restrict__ k,
            const float* __restrict__ v, const int* __restrict__ t_len,
            const int* __restrict__ ridx, float* __restrict__ o) {
    const int n = blockIdx.x, h = blockIdx.y, b = blockIdx.z;
    extern __shared__ float sm[];
    float* Qs = sm + SM_QS;
    float* Ks = sm + SM_KS;
    float* Vs = sm + SM_VS;
    float* Ps = sm + SM_PS;
    float* Pmax = sm + SM_MAX;
    float* Psum = sm + SM_SUM;

    const int tid = threadIdx.x;
    const int wid = tid >> 5, lane = tid & 31;
    const int g = lane >> 2, t = lane & 3;
    const int mw = wid >> 1;       // 0..3
    const int half = wid & 1;      // 0..1
    const int tlen = t_len[b];
    const int rn = ridx[n];
    const int chan = h * DHh;
    const int r0 = mw * 16 + g;    // row this thread covers (and r0+8)

    // ---- load Q [64][64], K & V [128][64] (rows 64.. = random bucket) ----
    for (int it = tid; it < 64 * 16; it += 256) {
        int r = it >> 4, c4 = (it & 15) * 4;
        *(float4*)(Qs + r * QS_STRIDE + c4) =
            *(const float4*)(q + ((size_t)(n * 64 + r) * Bb + b) * Dd + chan + c4);
    }
    for (int it = tid; it < 128 * 16; it += 256) {
        int r = it >> 4, c4 = (it & 15) * 4;
        int tt = (r < 64) ? n * 64 + r : rn * 64 + (r - 64);
        size_t base = ((size_t)tt * Bb + b) * Dd + chan + c4;
        *(float4*)(Ks + r * KS_STRIDE + c4) = *(const float4*)(k + base);
        *(float4*)(Vs + r * VS_STRIDE + c4) = *(const float4*)(v + base);
    }
    __syncthreads();

    // ---- S = Q @ K^T on this warp's 16x64 slab ----
    float acc[8][4];
    #pragma unroll
    for (int nt = 0; nt < 8; nt++)
        #pragma unroll
        for (int c = 0; c < 4; c++) acc[nt][c] = 0.f;

    #pragma unroll
    for (int k8 = 0; k8 < 8; k8++) {
        const int kk = k8 * 8;
        const float* Qr = Qs + r0 * QS_STRIDE;
        uint32_t af[4];
        af[0] = __float_as_uint(Qr[kk + t]);
        af[1] = __float_as_uint(Qr[8 * QS_STRIDE + kk + t]);
        af[2] = __float_as_uint(Qr[kk + t + 4]);
        af[3] = __float_as_uint(Qr[8 * QS_STRIDE + kk + t + 4]);
        #pragma unroll
        for (int nt = 0; nt < 8; nt++) {
            const int j = half * 64 + nt * 8 + g;
            uint32_t bf[2];
            bf[0] = __float_as_uint(Ks[j * KS_STRIDE + kk + t]);
            bf[1] = __float_as_uint(Ks[j * KS_STRIDE + kk + t + 4]);
            mma_tf32(acc[nt], af, bf);
        }
    }

    // ---- scale + mask, thread-local max ----
    float mx0 = -3.4e38f, mx1 = -3.4e38f;
    #pragma unroll
    for (int nt = 0; nt < 8; nt++) {
        const int j0 = half * 64 + nt * 8 + 2 * t;     // cols j0, j0+1 same bucket
        const int kp0 = (j0 < 64) ? n * 64 + j0 : rn * 64 + (j0 - 64);
        const bool v0 = kp0 < tlen, v1 = (kp0 + 1) < tlen;
        acc[nt][0] = v0 ? acc[nt][0] * 0.125f : -1e9f;
        acc[nt][1] = v1 ? acc[nt][1] * 0.125f : -1e9f;
        acc[nt][2] = v0 ? acc[nt][2] * 0.125f : -1e9f;
        acc[nt][3] = v1 ? acc[nt][3] * 0.125f : -1e9f;
        mx0 = fmaxf(mx0, fmaxf(acc[nt][0], acc[nt][1]));
        mx1 = fmaxf(mx1, fmaxf(acc[nt][2], acc[nt][3]));
    }
    // quad reduce across t (lanes xor 1, 2)
    mx0 = fmaxf(mx0, __shfl_xor_sync(~0u, mx0, 1));
    mx0 = fmaxf(mx0, __shfl_xor_sync(~0u, mx0, 2));
    mx1 = fmaxf(mx1, __shfl_xor_sync(~0u, mx1, 1));
    mx1 = fmaxf(mx1, __shfl_xor_sync(~0u, mx1, 2));
    if (t == 0) { Pmax[half * 64 + r0] = mx0; Pmax[half * 64 + r0 + 8] = mx1; }
    __syncthreads();
    const float rmx0 = fmaxf(Pmax[r0], Pmax[64 + r0]);
    const float rmx1 = fmaxf(Pmax[r0 + 8], Pmax[64 + r0 + 8]);

    // ---- exp + partial row sums ----
    float s0 = 0.f, s1 = 0.f;
    #pragma unroll
    for (int nt = 0; nt < 8; nt++) {
        acc[nt][0] = expf(acc[nt][0] - rmx0);
        acc[nt][1] = expf(acc[nt][1] - rmx0);
        acc[nt][2] = expf(acc[nt][2] - rmx1);
        acc[nt][3] = expf(acc[nt][3] - rmx1);
        s0 += acc[nt][0] + acc[nt][1];
        s1 += acc[nt][2] + acc[nt][3];
    }
    s0 += __shfl_xor_sync(~0u, s0, 1);
    s0 += __shfl_xor_sync(~0u, s0, 2);
    s1 += __shfl_xor_sync(~0u, s1, 1);
    s1 += __shfl_xor_sync(~0u, s1, 2);
    if (t == 0) { Psum[half * 64 + r0] = s0; Psum[half * 64 + r0 + 8] = s1; }
    __syncthreads();
    const float inv0 = 1.f / (Psum[r0] + Psum[64 + r0]);
    const float inv1 = 1.f / (Psum[r0 + 8] + Psum[64 + r0 + 8]);

    // ---- store normalized P to smem ----
    #pragma unroll
    for (int nt = 0; nt < 8; nt++) {
        const int j0 = half * 64 + nt * 8 + 2 * t;
        float2 p0; p0.x = acc[nt][0] * inv0; p0.y = acc[nt][1] * inv0;
        float2 p1; p1.x = acc[nt][2] * inv1; p1.y = acc[nt][3] * inv1;
        *(float2*)(Ps + r0 * PS_STRIDE + j0)       = p0;
        *(float2*)(Ps + (r0 + 8) * PS_STRIDE + j0) = p1;
    }
    __syncthreads();

    // ---- O = P @ V on this warp's 16x32 slab ----
    float acc2[4][4];
    #pragma unroll
    for (int nt = 0; nt < 4; nt++)
        #pragma unroll
        for (int c = 0; c < 4; c++) acc2[nt][c] = 0.f;

    #pragma unroll
    for (int k8 = 0; k8 < 16; k8++) {
        const int kk = k8 * 8;
        const float* Pr = Ps + r0 * PS_STRIDE;
        uint32_t af[4];
        af[0] = __float_as_uint(Pr[kk + t]);
        af[1] = __float_as_uint(Pr[8 * PS_STRIDE + kk + t]);
        af[2] = __float_as_uint(Pr[kk + t + 4]);
        af[3] = __float_as_uint(Pr[8 * PS_STRIDE + kk + t + 4]);
        #pragma unroll
        for (int nt = 0; nt < 4; nt++) {
            const int dh = half * 32 + nt * 8 + g;
            uint32_t bf[2];
            bf[0] = __float_as_uint(Vs[(kk + t) * VS_STRIDE + dh]);
            bf[1] = __float_as_uint(Vs[(kk + t + 4) * VS_STRIDE + dh]);
            mma_tf32(acc2[nt], af, bf);
        }
    }

    // ---- write O ----
    #pragma unroll
    for (int nt = 0; nt < 4; nt++) {
        const int col = chan + half * 32 + nt * 8 + 2 * t;
        const int tg = n * 64 + r0;
        float2 p0; p0.x = acc2[nt][0]; p0.y = acc2[nt][1];
        float2 p1; p1.x = acc2[nt][2]; p1.y = acc2[nt][3];
        *(float2*)(o + ((size_t)tg * Bb + b) * Dd + col)       = p0;
        *(float2*)(o + ((size_t)(tg + 8) * Bb + b) * Dd + col) = p1;
    }
}

// ---------------- residual + LayerNorm --------------------------------------
__global__ void __launch_bounds__(128)
res_ln_kernel(const float* __restrict__ a, const float* __restrict__ res,
              const float* __restrict__ g, const float* __restrict__ bt,
              float* __restrict__ out) {
    const int row = blockIdx.x;
    const int tid = threadIdx.x;
    const size_t base = (size_t)row * Dd;

    float4 va = *(const float4*)(a   + base + tid * 4);
    float4 vr = *(const float4*)(res + base + tid * 4);
    float x0 = va.x + vr.x, x1 = va.y + vr.y, x2 = va.z + vr.z, x3 = va.w + vr.w;

    float s  = x0 + x1 + x2 + x3;
    float sq = x0*x0 + x1*x1 + x2*x2 + x3*x3;

    const int lane = tid & 31, warp = tid >> 5;
    #pragma unroll
    for (int off = 16; off; off >>= 1) {
        s  += __shfl_xor_sync(~0u, s, off);
        sq += __shfl_xor_sync(~0u, sq, off);
    }
    __shared__ float ss[4], sqs[4];
    if (lane == 0) { ss[warp] = s; sqs[warp] = sq; }
    __syncthreads();
    s  = ss[0] + ss[1] + ss[2] + ss[3];
    sq = sqs[0] + sqs[1] + sqs[2] + sqs[3];

    float mean = s * (1.f / Dd);
    float var  = sq * (1.f / Dd) - mean * mean;
    float rs   = rsqrtf(var + LNEPS);

    float4 gg = *(const float4*)(g  + tid * 4);
    float4 bb = *(const float4*)(bt + tid * 4);
    float4 r;
    r.x = (x0 - mean) * rs * gg.x + bb.x;
    r.y = (x1 - mean) * rs * gg.y + bb.y;
    r.z = (x2 - mean) * rs * gg.z + bb.z;
    r.w = (x3 - mean) * rs * gg.w + bb.w;
    *(float4*)(out + base + tid * 4) = r;
}

// ---------------- launch ----------------------------------------------------
extern "C" void kernel_launch(void* const* d_in, const int* in_sizes, int n_in,
                              void* d_out, int out_size) {
    const float* x        = (const float*)d_in[0];
    const int*   t_length = (const int*)  d_in[1];
    const int*   rand_idx = (const int*)  d_in[2];
    const float* conv_w   = (const float*)d_in[3];
    const float* bn_g     = (const float*)d_in[4];
    const float* bn_b     = (const float*)d_in[5];
    const float* bn_m     = (const float*)d_in[6];
    const float* bn_v     = (const float*)d_in[7];
    const float* wq = (const float*)d_in[8];  const float* bq = (const float*)d_in[9];
    const float* wk = (const float*)d_in[10]; const float* bk = (const float*)d_in[11];
    const float* wv = (const float*)d_in[12]; const float* bv = (const float*)d_in[13];
    const float* wo = (const float*)d_in[14]; const float* bo = (const float*)d_in[15];
    const float* ln1_g = (const float*)d_in[16]; const float* ln1_b = (const float*)d_in[17];
    const float* w1 = (const float*)d_in[18]; const float* b1 = (const float*)d_in[19];
    const float* w2 = (const float*)d_in[20]; const float* b2 = (const float*)d_in[21];
    const float* ln2_g = (const float*)d_in[22]; const float* ln2_b = (const float*)d_in[23];
    float* out = (float*)d_out;

    static float* p_base = nullptr;
    if (p_base == nullptr) {
        cudaGetSymbolAddress((void**)&p_base, g_scratch);
        cudaFuncSetAttribute((const void*)attn_kernel,
                             cudaFuncAttributeMaxDynamicSharedMemorySize, ATTN_SMEM);
        cudaFuncSetAttribute((const void*)mma_gemm_kernel<0>,
                             cudaFuncAttributeMaxDynamicSharedMemorySize, GEMM_SMEM);
        cudaFuncSetAttribute((const void*)mma_gemm_kernel<1>,
                             cudaFuncAttributeMaxDynamicSharedMemorySize, GEMM_SMEM);
    }
    float* p_xc = p_base;
    float* p_q  = p_base + SEG;       // reused as t1 after attention
    float* p_k  = p_base + SEG * 2;   // reused as h (spans k+v) after attention
    float* p_v  = p_base + SEG * 3;
    float* p_o  = p_base + SEG * 4;
    float* p_x1 = p_base + SEG * 5;
    float* p_t1 = p_q;
    float* p_h  = p_k;

    // 1) conv + residual + BN
    conv_bn_kernel<<<(TBr * Dd) / 256, 256>>>(x, conv_w, bn_g, bn_b, bn_m, bn_v, p_xc);

    // 2) QKV projections
    {
        dim3 grid(Dd / 128, TBr / 128);
        mma_gemm_kernel<0><<<grid, 256, GEMM_SMEM>>>(TBr, Dd, Dd, p_xc, wq, bq, p_q);
        mma_gemm_kernel<0><<<grid, 256, GEMM_SMEM>>>(TBr, Dd, Dd, p_xc, wk, bk, p_k);
        mma_gemm_kernel<0><<<grid, 256, GEMM_SMEM>>>(TBr, Dd, Dd, p_xc, wv, bv, p_v);
    }

    // 3) bucketed attention (tensor cores)
    {
        dim3 grid(NBn, Hh, Bb);
        attn_kernel<<<grid, 256, ATTN_SMEM>>>(p_q, p_k, p_v, t_length, rand_idx, p_o);
    }

    // 4) O projection
    {
        dim3 grid(Dd / 128, TBr / 128);
        mma_gemm_kernel<0><<<grid, 256, GEMM_SMEM>>>(TBr, Dd, Dd, p_o, wo, bo, p_t1);
    }

    // 5) residual + LN1
    res_ln_kernel<<<TBr, 128>>>(p_t1, p_xc, ln1_g, ln1_b, p_x1);

    // 6) MLP up (GeLU fused)
    {
        dim3 grid((2 * Dd) / 128, TBr / 128);
        mma_gemm_kernel<1><<<grid, 256, GEMM_SMEM>>>(TBr, 2 * Dd, Dd, p_x1, w1, b1, p_h);
    }

    // 7) MLP down
    {
        dim3 grid(Dd / 128, TBr / 128);
        mma_gemm_kernel<0><<<grid, 256, GEMM_SMEM>>>(TBr, Dd, 2 * Dd, p_h, w2, b2, p_t1);
    }

    // 8) residual + LN2 -> output
    res_ln_kernel<<<TBr, 128>>>(p_t1, p_x1, ln2_g, ln2_b, out);
}